// round 2
// baseline (speedup 1.0000x reference)
#include <cuda_runtime.h>

#define NN 100000
#define EE 1600000
#define EPS 1e-5f

// ---------------- scratch (static device globals; no allocation allowed) ----
__device__ float g_bufA[NN * 256];     // mlp hidden
__device__ float g_zmlp[NN * 128];     // mlp out
__device__ float g_hin[NN * 64];       // asda output
__device__ float g_xr[3 * NN * 128];   // per-relation transformed features
__device__ float g_agg1[NN * 128];     // rgcn1 out / z1
__device__ float g_agg2[NN * 128];     // rgcn2 out / z2
__device__ float g_e[EE];              // per-edge exp
__device__ float g_den[NN];            // softmax denominators
__device__ float g_cnt[3 * NN];        // per (rel,node) inverse counts
__device__ float g_sum[4 * 256];       // bn stats (4 stages)
__device__ float g_sq[4 * 256];

// ---------------- utility kernels ------------------------------------------
__global__ void k_zero(float* p, int n) {
    int i = blockIdx.x * blockDim.x + threadIdx.x;
    if (i < n) p[i] = 0.0f;
}

__global__ void k_copy(float* dst, const float* __restrict__ src, int n) {
    int i = blockIdx.x * blockDim.x + threadIdx.x;
    if (i < n) dst[i] = src[i];
}

// ---------------- SGEMM: C = A(MxK) * B(KxNc) + bias, batched over z --------
#define BM 128
#define BN 128
#define BKK 16
#define TM 8
#define TN 8

__global__ __launch_bounds__(256)
void sgemm_bias(const float* __restrict__ A, const float* __restrict__ B,
                const float* __restrict__ bias, float* __restrict__ C,
                int M, int K, int Nc, long strideB, long strideC) {
    int batch = blockIdx.z;
    B += (long)batch * strideB;
    C += (long)batch * strideC;

    __shared__ float As[BKK][BM];  // transposed A tile
    __shared__ float Bs[BKK][BN];

    int tid = threadIdx.x;
    int tcol = tid % (BN / TN);  // 0..15
    int trow = tid / (BN / TN);  // 0..15
    int rowBase = blockIdx.y * BM;
    int colBase = blockIdx.x * BN;

    float acc[TM][TN];
#pragma unroll
    for (int i = 0; i < TM; i++)
#pragma unroll
        for (int j = 0; j < TN; j++) acc[i][j] = 0.0f;

    int aRow = tid / 4;       // 0..63 (two iters of +64)
    int aCol4 = tid % 4;      // float4 within 16-wide K slab
    int bRow = tid / 32;      // 0..7 (two iters of +8)
    int bCol4 = tid % 32;

    for (int k0 = 0; k0 < K; k0 += BKK) {
#pragma unroll
        for (int i = 0; i < 2; i++) {
            int r = aRow + i * 64;
            int grow = rowBase + r;
            float4 v = make_float4(0.f, 0.f, 0.f, 0.f);
            if (grow < M) v = *(const float4*)&A[(long)grow * K + k0 + aCol4 * 4];
            As[aCol4 * 4 + 0][r] = v.x;
            As[aCol4 * 4 + 1][r] = v.y;
            As[aCol4 * 4 + 2][r] = v.z;
            As[aCol4 * 4 + 3][r] = v.w;
        }
#pragma unroll
        for (int i = 0; i < 2; i++) {
            int r = bRow + i * 8;
            float4 v = *(const float4*)&B[(long)(k0 + r) * Nc + colBase + bCol4 * 4];
            *(float4*)&Bs[r][bCol4 * 4] = v;
        }
        __syncthreads();

#pragma unroll
        for (int kk = 0; kk < BKK; kk++) {
            float ra[TM], rb[TN];
            *(float4*)&ra[0] = *(const float4*)&As[kk][trow * TM];
            *(float4*)&ra[4] = *(const float4*)&As[kk][trow * TM + 4];
            *(float4*)&rb[0] = *(const float4*)&Bs[kk][tcol * TN];
            *(float4*)&rb[4] = *(const float4*)&Bs[kk][tcol * TN + 4];
#pragma unroll
            for (int i = 0; i < TM; i++)
#pragma unroll
                for (int j = 0; j < TN; j++) acc[i][j] = fmaf(ra[i], rb[j], acc[i][j]);
        }
        __syncthreads();
    }

#pragma unroll
    for (int i = 0; i < TM; i++) {
        int grow = rowBase + trow * TM + i;
        if (grow >= M) continue;
#pragma unroll
        for (int j = 0; j < TN; j++) {
            int col = colBase + tcol * TN + j;
            float bv = bias ? bias[col] : 0.0f;
            C[(long)grow * Nc + col] = acc[i][j] + bv;
        }
    }
}

// ---------------- BN stats + normalize-relu --------------------------------
__global__ void k_colstats(const float* __restrict__ z, float* sum, float* sq) {
    int C = blockDim.x;
    int t = threadIdx.x;
    float s = 0.f, q = 0.f;
    for (int r = blockIdx.x; r < NN; r += gridDim.x) {
        float v = z[(long)r * C + t];
        s += v;
        q += v * v;
    }
    atomicAdd(&sum[t], s);
    atomicAdd(&sq[t], q);
}

__global__ void k_bnrelu(float* z, int C, const float* __restrict__ sum,
                         const float* __restrict__ sq, const float* __restrict__ gam,
                         const float* __restrict__ bet, int total) {
    int i = blockIdx.x * blockDim.x + threadIdx.x;
    if (i >= total) return;
    int c = i % C;
    const float invN = 1.0f / (float)NN;
    float m = sum[c] * invN;
    float var = sq[c] * invN - m * m;
    float v = (z[i] - m) * rsqrtf(var + EPS) * gam[c] + bet[c];
    z[i] = fmaxf(v, 0.0f);
}

// ---------------- ASDA ------------------------------------------------------
__global__ void k_edge_e(const float* __restrict__ hsd, const int* __restrict__ src,
                         const int* __restrict__ dst) {
    int i = blockIdx.x * blockDim.x + threadIdx.x;
    if (i >= EE) return;
    float s = (hsd[src[i]] - hsd[dst[i]]) * 10.0f;  // 1/TAU
    float e = expf(s);
    g_e[i] = e;
    atomicAdd(&g_den[dst[i]], e);
}

__global__ void k_asda(const float* __restrict__ x, const int* __restrict__ src,
                       const int* __restrict__ dst) {
    int g = blockIdx.x * blockDim.x + threadIdx.x;
    int edge = g >> 4;
    int sub = g & 15;
    if (edge >= EE) return;
    int s = src[edge], d = dst[edge];
    float a = g_e[edge] / fmaxf(g_den[d], 1e-9f);
    float4 v = *(const float4*)&x[s * 64 + sub * 4];
    float* o = &g_hin[(long)d * 64 + sub * 4];
    atomicAdd(o + 0, v.x * a);
    atomicAdd(o + 1, v.y * a);
    atomicAdd(o + 2, v.z * a);
    atomicAdd(o + 3, v.w * a);
}

// ---------------- RGCN count + scatter --------------------------------------
__global__ void k_cnt(const int* __restrict__ dst, const int* __restrict__ et) {
    int i = blockIdx.x * blockDim.x + threadIdx.x;
    if (i >= EE) return;
    atomicAdd(&g_cnt[et[i] * NN + dst[i]], 1.0f);
}

__global__ void k_invcnt() {
    int i = blockIdx.x * blockDim.x + threadIdx.x;
    if (i >= 3 * NN) return;
    g_cnt[i] = 1.0f / fmaxf(g_cnt[i], 1.0f);
}

__global__ void k_rgcn_scatter(const float* __restrict__ xr, float* agg,
                               const int* __restrict__ src, const int* __restrict__ dst,
                               const int* __restrict__ et) {
    int g = blockIdx.x * blockDim.x + threadIdx.x;
    int edge = g >> 5;
    int lane = g & 31;
    if (edge >= EE) return;
    int s = src[edge], d = dst[edge], r = et[edge];
    float w = g_cnt[r * NN + d];
    float4 v = *(const float4*)&xr[((long)r * NN + s) * 128 + lane * 4];
    float* o = &agg[(long)d * 128 + lane * 4];
    atomicAdd(o + 0, v.x * w);
    atomicAdd(o + 1, v.y * w);
    atomicAdd(o + 2, v.z * w);
    atomicAdd(o + 3, v.w * w);
}

// ---------------- final head -------------------------------------------------
__global__ void k_final(const float* __restrict__ ow, const float* __restrict__ ob,
                        float* __restrict__ out) {
    int g = blockIdx.x * blockDim.x + threadIdx.x;
    int node = g >> 5;
    int lane = g & 31;
    if (node >= NN) return;
    float4 a = *(const float4*)&g_zmlp[(long)node * 128 + lane * 4];
    float4 w1 = *(const float4*)&ow[lane * 4];
    float4 b = *(const float4*)&g_agg2[(long)node * 128 + lane * 4];
    float4 w2 = *(const float4*)&ow[128 + lane * 4];
    float sum = a.x * w1.x + a.y * w1.y + a.z * w1.z + a.w * w1.w +
                b.x * w2.x + b.y * w2.y + b.z * w2.z + b.w * w2.w;
#pragma unroll
    for (int off = 16; off > 0; off >>= 1) sum += __shfl_down_sync(0xffffffff, sum, off);
    if (lane == 0) out[node] = sum + ob[0];
}

// ---------------- host ------------------------------------------------------
extern "C" void kernel_launch(void* const* d_in, const int* in_sizes, int n_in,
                              void* d_out, int out_size) {
    const float* x       = (const float*)d_in[0];
    const float* hsd     = (const float*)d_in[1];
    const int*   ei      = (const int*)d_in[2];
    const int*   et      = (const int*)d_in[3];
    const float* mlp_w1  = (const float*)d_in[4];
    const float* mlp_b1  = (const float*)d_in[5];
    const float* mlp_g1  = (const float*)d_in[6];
    const float* mlp_be1 = (const float*)d_in[7];
    const float* mlp_w2  = (const float*)d_in[8];
    const float* mlp_b2  = (const float*)d_in[9];
    const float* mlp_g2  = (const float*)d_in[10];
    const float* mlp_be2 = (const float*)d_in[11];
    const float* rg1_wrel  = (const float*)d_in[12];
    const float* rg1_wroot = (const float*)d_in[13];
    const float* rg1_b     = (const float*)d_in[14];
    const float* bn1_g     = (const float*)d_in[15];
    const float* bn1_b     = (const float*)d_in[16];
    const float* rg2_wrel  = (const float*)d_in[17];
    const float* rg2_wroot = (const float*)d_in[18];
    const float* rg2_b     = (const float*)d_in[19];
    const float* bn2_g     = (const float*)d_in[20];
    const float* bn2_b     = (const float*)d_in[21];
    const float* out_w     = (const float*)d_in[22];
    const float* out_b     = (const float*)d_in[23];
    const int* src = ei;
    const int* dst = ei + EE;
    float* out = (float*)d_out;

    float *bufA, *zmlp, *hin, *xr, *agg1, *agg2, *den, *cnt, *sum, *sq;
    cudaGetSymbolAddress((void**)&bufA, g_bufA);
    cudaGetSymbolAddress((void**)&zmlp, g_zmlp);
    cudaGetSymbolAddress((void**)&hin, g_hin);
    cudaGetSymbolAddress((void**)&xr, g_xr);
    cudaGetSymbolAddress((void**)&agg1, g_agg1);
    cudaGetSymbolAddress((void**)&agg2, g_agg2);
    cudaGetSymbolAddress((void**)&den, g_den);
    cudaGetSymbolAddress((void**)&cnt, g_cnt);
    cudaGetSymbolAddress((void**)&sum, g_sum);
    cudaGetSymbolAddress((void**)&sq, g_sq);

    const int T = 256;
    int gy = (NN + BM - 1) / BM;  // 782

    // zero accumulators / stats
    k_zero<<<(NN + T - 1) / T, T>>>(den, NN);
    k_zero<<<(3 * NN + T - 1) / T, T>>>(cnt, 3 * NN);
    k_zero<<<(1024 + T - 1) / T, T>>>(sum, 1024);
    k_zero<<<(1024 + T - 1) / T, T>>>(sq, 1024);
    k_copy<<<(NN * 64 + T - 1) / T, T>>>(hin, x, NN * 64);

    // ---- MLP branch ----
    sgemm_bias<<<dim3(2, gy, 1), T>>>(x, mlp_w1, mlp_b1, bufA, NN, 64, 256, 0, 0);
    k_colstats<<<512, 256>>>(bufA, sum + 0, sq + 0);
    k_bnrelu<<<(NN * 256 + T - 1) / T, T>>>(bufA, 256, sum + 0, sq + 0, mlp_g1, mlp_be1, NN * 256);
    sgemm_bias<<<dim3(1, gy, 1), T>>>(bufA, mlp_w2, mlp_b2, zmlp, NN, 256, 128, 0, 0);
    k_colstats<<<512, 128>>>(zmlp, sum + 256, sq + 256);
    k_bnrelu<<<(NN * 128 + T - 1) / T, T>>>(zmlp, 128, sum + 256, sq + 256, mlp_g2, mlp_be2, NN * 128);

    // ---- ASDA (softmax without segment_max: shift-invariant, s in [-10,10]) ----
    k_edge_e<<<(EE + T - 1) / T, T>>>(hsd, src, dst);
    k_asda<<<((long)EE * 16 + T - 1) / T, T>>>(x, src, dst);

    // ---- per-(rel,node) counts (shared by both layers) ----
    k_cnt<<<(EE + T - 1) / T, T>>>(dst, et);
    k_invcnt<<<(3 * NN + T - 1) / T, T>>>();

    // ---- RGCN layer 1 ----
    sgemm_bias<<<dim3(1, gy, 3), T>>>(hin, rg1_wrel, nullptr, xr, NN, 64, 128,
                                      (long)64 * 128, (long)NN * 128);
    sgemm_bias<<<dim3(1, gy, 1), T>>>(hin, rg1_wroot, rg1_b, agg1, NN, 64, 128, 0, 0);
    k_rgcn_scatter<<<((long)EE * 32 + T - 1) / T, T>>>(xr, agg1, src, dst, et);
    k_colstats<<<512, 128>>>(agg1, sum + 512, sq + 512);
    k_bnrelu<<<(NN * 128 + T - 1) / T, T>>>(agg1, 128, sum + 512, sq + 512, bn1_g, bn1_b, NN * 128);

    // ---- RGCN layer 2 ----
    sgemm_bias<<<dim3(1, gy, 3), T>>>(agg1, rg2_wrel, nullptr, xr, NN, 128, 128,
                                      (long)128 * 128, (long)NN * 128);
    sgemm_bias<<<dim3(1, gy, 1), T>>>(agg1, rg2_wroot, rg2_b, agg2, NN, 128, 128, 0, 0);
    k_rgcn_scatter<<<((long)EE * 32 + T - 1) / T, T>>>(xr, agg2, src, dst, et);
    k_colstats<<<512, 128>>>(agg2, sum + 768, sq + 768);
    k_bnrelu<<<(NN * 128 + T - 1) / T, T>>>(agg2, 128, sum + 768, sq + 768, bn2_g, bn2_b, NN * 128);

    // ---- head ----
    k_final<<<((long)NN * 32 + T - 1) / T, T>>>(out_w, out_b, out);
}

// round 3
// speedup vs baseline: 1.6041x; 1.6041x over previous
#include <cuda_runtime.h>

#define NN 100000
#define EE 1600000
#define EPS 1e-5f
#define NB1 196   // ceil(NN/512)

// ---------------- scratch ---------------------------------------------------
__device__ float g_bufA[NN * 256];     // MLP hidden, then A1 = [agg_r0|agg_r1|agg_r2|h_in]
__device__ float g_zmlp[NN * 128];
__device__ float g_A2[(long)NN * 512]; // [agg_r0|agg_r1|agg_r2|z1]
__device__ float g_agg1[NN * 128];     // z1
__device__ float g_agg2[NN * 128];     // z2
__device__ float g_wcat[256 * 128 + 512 * 128];
__device__ float g_sum[4 * 256];
__device__ float g_sq[4 * 256];
__device__ int   g_hist[NN];
__device__ int   g_row[NN];
__device__ int   g_cur[NN];
__device__ int   g_incl[NN];
__device__ int   g_bsum[256];
__device__ int   g_packed[EE];         // src | (rel<<20)

// ---------------- utility ---------------------------------------------------
__global__ void k_zero_i(int* p, int n) {
    int i = blockIdx.x * blockDim.x + threadIdx.x;
    if (i < n) p[i] = 0;
}
__global__ void k_zero_f(float* p, int n) {
    int i = blockIdx.x * blockDim.x + threadIdx.x;
    if (i < n) p[i] = 0.0f;
}
__global__ void k_copy(float* dst, const float* __restrict__ src, int n) {
    int i = blockIdx.x * blockDim.x + threadIdx.x;
    if (i < n) dst[i] = src[i];
}

// ---------------- CSR build --------------------------------------------------
__global__ void k_hist(const int* __restrict__ dst) {
    int i = blockIdx.x * blockDim.x + threadIdx.x;
    if (i < EE) atomicAdd(&g_hist[dst[i]], 1);
}
__global__ void k_scan1() {
    __shared__ int sm[512];
    int i = blockIdx.x * 512 + threadIdx.x;
    int v = (i < NN) ? g_hist[i] : 0;
    sm[threadIdx.x] = v;
    __syncthreads();
    for (int off = 1; off < 512; off <<= 1) {
        int t = (threadIdx.x >= off) ? sm[threadIdx.x - off] : 0;
        __syncthreads();
        sm[threadIdx.x] += t;
        __syncthreads();
    }
    if (i < NN) g_incl[i] = sm[threadIdx.x];
    if (threadIdx.x == 511) g_bsum[blockIdx.x] = sm[511];
}
__global__ void k_scan2() {
    __shared__ int sm[256];
    int t = threadIdx.x;
    int v = (t < NB1) ? g_bsum[t] : 0;
    sm[t] = v;
    __syncthreads();
    for (int off = 1; off < 256; off <<= 1) {
        int u = (t >= off) ? sm[t - off] : 0;
        __syncthreads();
        sm[t] += u;
        __syncthreads();
    }
    if (t < NB1) g_bsum[t] = sm[t] - v;  // exclusive
}
__global__ void k_scan3() {
    int i = blockIdx.x * 512 + threadIdx.x;
    if (i >= NN) return;
    int r = g_incl[i] - g_hist[i] + g_bsum[blockIdx.x];
    g_row[i] = r;
    g_cur[i] = r;
}
__global__ void k_place(const int* __restrict__ src, const int* __restrict__ dst,
                        const int* __restrict__ et) {
    int i = blockIdx.x * blockDim.x + threadIdx.x;
    if (i >= EE) return;
    int pos = atomicAdd(&g_cur[dst[i]], 1);
    g_packed[pos] = src[i] | (et[i] << 20);
}

// ---------------- SGEMM ------------------------------------------------------
#define BM 128
#define BN 128
#define BKK 16
#define TM 8
#define TN 8

__global__ __launch_bounds__(256)
void sgemm_bias(const float* __restrict__ A, const float* __restrict__ B,
                const float* __restrict__ bias, float* __restrict__ C,
                int M, int K, int Nc) {
    __shared__ float As[BKK][BM];
    __shared__ float Bs[BKK][BN];

    int tid = threadIdx.x;
    int tcol = tid % (BN / TN);
    int trow = tid / (BN / TN);
    int rowBase = blockIdx.y * BM;
    int colBase = blockIdx.x * BN;

    float acc[TM][TN];
#pragma unroll
    for (int i = 0; i < TM; i++)
#pragma unroll
        for (int j = 0; j < TN; j++) acc[i][j] = 0.0f;

    int aRow = tid / 4, aCol4 = tid % 4;
    int bRow = tid / 32, bCol4 = tid % 32;

    for (int k0 = 0; k0 < K; k0 += BKK) {
#pragma unroll
        for (int i = 0; i < 2; i++) {
            int r = aRow + i * 64;
            int grow = rowBase + r;
            float4 v = make_float4(0.f, 0.f, 0.f, 0.f);
            if (grow < M) v = *(const float4*)&A[(long)grow * K + k0 + aCol4 * 4];
            As[aCol4 * 4 + 0][r] = v.x;
            As[aCol4 * 4 + 1][r] = v.y;
            As[aCol4 * 4 + 2][r] = v.z;
            As[aCol4 * 4 + 3][r] = v.w;
        }
#pragma unroll
        for (int i = 0; i < 2; i++) {
            int r = bRow + i * 8;
            float4 v = *(const float4*)&B[(long)(k0 + r) * Nc + colBase + bCol4 * 4];
            *(float4*)&Bs[r][bCol4 * 4] = v;
        }
        __syncthreads();

#pragma unroll
        for (int kk = 0; kk < BKK; kk++) {
            float ra[TM], rb[TN];
            *(float4*)&ra[0] = *(const float4*)&As[kk][trow * TM];
            *(float4*)&ra[4] = *(const float4*)&As[kk][trow * TM + 4];
            *(float4*)&rb[0] = *(const float4*)&Bs[kk][tcol * TN];
            *(float4*)&rb[4] = *(const float4*)&Bs[kk][tcol * TN + 4];
#pragma unroll
            for (int i = 0; i < TM; i++)
#pragma unroll
                for (int j = 0; j < TN; j++) acc[i][j] = fmaf(ra[i], rb[j], acc[i][j]);
        }
        __syncthreads();
    }

#pragma unroll
    for (int i = 0; i < TM; i++) {
        int grow = rowBase + trow * TM + i;
        if (grow >= M) continue;
#pragma unroll
        for (int j = 0; j < TN; j++) {
            int col = colBase + tcol * TN + j;
            C[(long)grow * Nc + col] = acc[i][j] + bias[col];
        }
    }
}

// ---------------- BN ---------------------------------------------------------
__global__ void k_colstats(const float* __restrict__ z, float* sum, float* sq) {
    int C = blockDim.x;
    int t = threadIdx.x;
    float s = 0.f, q = 0.f;
    for (int r = blockIdx.x; r < NN; r += gridDim.x) {
        float v = z[(long)r * C + t];
        s += v;
        q += v * v;
    }
    atomicAdd(&sum[t], s);
    atomicAdd(&sq[t], q);
}
__global__ void k_bnrelu(float* z, int C, const float* __restrict__ sum,
                         const float* __restrict__ sq, const float* __restrict__ gam,
                         const float* __restrict__ bet, int total) {
    int i = blockIdx.x * blockDim.x + threadIdx.x;
    if (i >= total) return;
    int c = i % C;
    const float invN = 1.0f / (float)NN;
    float m = sum[c] * invN;
    float var = sq[c] * invN - m * m;
    float v = (z[i] - m) * rsqrtf(var + EPS) * gam[c] + bet[c];
    z[i] = fmaxf(v, 0.0f);
}

// ---------------- ASDA (CSR, warp per node) ---------------------------------
__global__ __launch_bounds__(256)
void k_asda(const float* __restrict__ x, const float* __restrict__ hsd) {
    int node = (blockIdx.x * blockDim.x + threadIdx.x) >> 5;
    int lane = threadIdx.x & 31;
    if (node >= NN) return;
    int start = g_row[node];
    int end = start + g_hist[node];
    float hd = hsd[node];

    float den = 0.f;
    for (int base = start; base < end; base += 32) {
        int idx = base + lane;
        float e = 0.f;
        if (idx < end) {
            int s = g_packed[idx] & 0xFFFFF;
            e = __expf((hsd[s] - hd) * 10.0f);
        }
        den += e;
    }
#pragma unroll
    for (int o = 16; o > 0; o >>= 1) den += __shfl_xor_sync(0xffffffffu, den, o);
    float inv = 1.0f / fmaxf(den, 1e-9f);

    float a0 = x[(long)node * 64 + lane];
    float a1 = x[(long)node * 64 + 32 + lane];
    for (int base = start; base < end; base += 32) {
        int idx = base + lane;
        int v = 0;
        float al = 0.f;
        if (idx < end) {
            v = g_packed[idx];
            int s = v & 0xFFFFF;
            al = __expf((hsd[s] - hd) * 10.0f) * inv;
        }
        int m = min(32, end - base);
        for (int j = 0; j < m; j++) {
            int vv = __shfl_sync(0xffffffffu, v, j);
            float aa = __shfl_sync(0xffffffffu, al, j);
            int s = vv & 0xFFFFF;
            a0 = fmaf(aa, x[(long)s * 64 + lane], a0);
            a1 = fmaf(aa, x[(long)s * 64 + 32 + lane], a1);
        }
    }
    g_bufA[(long)node * 256 + 192 + lane] = a0;   // h_in -> A1 slot 3
    g_bufA[(long)node * 256 + 224 + lane] = a1;
}

// ---------------- RGCN layer-1 input aggregation (dim 64) --------------------
__global__ __launch_bounds__(256)
void k_agg1() {
    int node = (blockIdx.x * blockDim.x + threadIdx.x) >> 5;
    int lane = threadIdx.x & 31;
    if (node >= NN) return;
    int start = g_row[node];
    int end = start + g_hist[node];

    float a00 = 0, a01 = 0, a10 = 0, a11 = 0, a20 = 0, a21 = 0;
    int c0 = 0, c1 = 0, c2 = 0;
    for (int base = start; base < end; base += 32) {
        int idx = base + lane;
        int v = (idx < end) ? g_packed[idx] : 0;
        int m = min(32, end - base);
        for (int j = 0; j < m; j++) {
            int vv = __shfl_sync(0xffffffffu, v, j);
            int s = vv & 0xFFFFF;
            int r = vv >> 20;
            float f0 = g_bufA[(long)s * 256 + 192 + lane];
            float f1 = g_bufA[(long)s * 256 + 224 + lane];
            if (r == 0)      { a00 += f0; a01 += f1; c0++; }
            else if (r == 1) { a10 += f0; a11 += f1; c1++; }
            else             { a20 += f0; a21 += f1; c2++; }
        }
    }
    float w0 = 1.0f / (float)max(c0, 1);
    float w1 = 1.0f / (float)max(c1, 1);
    float w2 = 1.0f / (float)max(c2, 1);
    long b = (long)node * 256;
    g_bufA[b + 0 + lane] = a00 * w0;  g_bufA[b + 32 + lane] = a01 * w0;
    g_bufA[b + 64 + lane] = a10 * w1; g_bufA[b + 96 + lane] = a11 * w1;
    g_bufA[b + 128 + lane] = a20 * w2; g_bufA[b + 160 + lane] = a21 * w2;
}

// ---------------- RGCN layer-2 input aggregation (dim 128) -------------------
__global__ __launch_bounds__(256)
void k_agg2() {
    int node = (blockIdx.x * blockDim.x + threadIdx.x) >> 5;
    int lane = threadIdx.x & 31;
    if (node >= NN) return;
    int start = g_row[node];
    int end = start + g_hist[node];

    float acc[3][4] = {};
    int cnt[3] = {0, 0, 0};
    for (int base = start; base < end; base += 32) {
        int idx = base + lane;
        int v = (idx < end) ? g_packed[idx] : 0;
        int m = min(32, end - base);
        for (int j = 0; j < m; j++) {
            int vv = __shfl_sync(0xffffffffu, v, j);
            int s = vv & 0xFFFFF;
            int r = vv >> 20;
            long sb = (long)s * 128;
            float f0 = g_agg1[sb + lane];
            float f1 = g_agg1[sb + 32 + lane];
            float f2 = g_agg1[sb + 64 + lane];
            float f3 = g_agg1[sb + 96 + lane];
            if (r == 0)      { acc[0][0] += f0; acc[0][1] += f1; acc[0][2] += f2; acc[0][3] += f3; cnt[0]++; }
            else if (r == 1) { acc[1][0] += f0; acc[1][1] += f1; acc[1][2] += f2; acc[1][3] += f3; cnt[1]++; }
            else             { acc[2][0] += f0; acc[2][1] += f1; acc[2][2] += f2; acc[2][3] += f3; cnt[2]++; }
        }
    }
    long b = (long)node * 512;
#pragma unroll
    for (int r = 0; r < 3; r++) {
        float w = 1.0f / (float)max(cnt[r], 1);
#pragma unroll
        for (int k = 0; k < 4; k++)
            g_A2[b + r * 128 + k * 32 + lane] = acc[r][k] * w;
    }
    long zb = (long)node * 128;
#pragma unroll
    for (int k = 0; k < 4; k++)
        g_A2[b + 384 + k * 32 + lane] = g_agg1[zb + k * 32 + lane];
}

// ---------------- head -------------------------------------------------------
__global__ void k_final(const float* __restrict__ ow, const float* __restrict__ ob,
                        float* __restrict__ out) {
    int g = blockIdx.x * blockDim.x + threadIdx.x;
    int node = g >> 5;
    int lane = g & 31;
    if (node >= NN) return;
    float4 a = *(const float4*)&g_zmlp[(long)node * 128 + lane * 4];
    float4 w1 = *(const float4*)&ow[lane * 4];
    float4 b = *(const float4*)&g_agg2[(long)node * 128 + lane * 4];
    float4 w2 = *(const float4*)&ow[128 + lane * 4];
    float sum = a.x * w1.x + a.y * w1.y + a.z * w1.z + a.w * w1.w +
                b.x * w2.x + b.y * w2.y + b.z * w2.z + b.w * w2.w;
#pragma unroll
    for (int off = 16; off > 0; off >>= 1) sum += __shfl_down_sync(0xffffffffu, sum, off);
    if (lane == 0) out[node] = sum + ob[0];
}

// ---------------- host -------------------------------------------------------
extern "C" void kernel_launch(void* const* d_in, const int* in_sizes, int n_in,
                              void* d_out, int out_size) {
    const float* x       = (const float*)d_in[0];
    const float* hsd     = (const float*)d_in[1];
    const int*   ei      = (const int*)d_in[2];
    const int*   et      = (const int*)d_in[3];
    const float* mlp_w1  = (const float*)d_in[4];
    const float* mlp_b1  = (const float*)d_in[5];
    const float* mlp_g1  = (const float*)d_in[6];
    const float* mlp_be1 = (const float*)d_in[7];
    const float* mlp_w2  = (const float*)d_in[8];
    const float* mlp_b2  = (const float*)d_in[9];
    const float* mlp_g2  = (const float*)d_in[10];
    const float* mlp_be2 = (const float*)d_in[11];
    const float* rg1_wrel  = (const float*)d_in[12];
    const float* rg1_wroot = (const float*)d_in[13];
    const float* rg1_b     = (const float*)d_in[14];
    const float* bn1_g     = (const float*)d_in[15];
    const float* bn1_b     = (const float*)d_in[16];
    const float* rg2_wrel  = (const float*)d_in[17];
    const float* rg2_wroot = (const float*)d_in[18];
    const float* rg2_b     = (const float*)d_in[19];
    const float* bn2_g     = (const float*)d_in[20];
    const float* bn2_b     = (const float*)d_in[21];
    const float* out_w     = (const float*)d_in[22];
    const float* out_b     = (const float*)d_in[23];
    const int* src = ei;
    const int* dst = ei + EE;
    float* out = (float*)d_out;

    float *bufA, *zmlp, *A2, *agg1, *agg2, *wcat, *sum, *sq;
    int *hist;
    cudaGetSymbolAddress((void**)&bufA, g_bufA);
    cudaGetSymbolAddress((void**)&zmlp, g_zmlp);
    cudaGetSymbolAddress((void**)&A2, g_A2);
    cudaGetSymbolAddress((void**)&agg1, g_agg1);
    cudaGetSymbolAddress((void**)&agg2, g_agg2);
    cudaGetSymbolAddress((void**)&wcat, g_wcat);
    cudaGetSymbolAddress((void**)&sum, g_sum);
    cudaGetSymbolAddress((void**)&sq, g_sq);
    cudaGetSymbolAddress((void**)&hist, g_hist);

    const int T = 256;
    int gy = (NN + BM - 1) / BM;  // 782
    float* wcat1 = wcat;
    float* wcat2 = wcat + 256 * 128;

    // zero stats + hist
    k_zero_f<<<(2048 + T - 1) / T, T>>>(sum, 1024);   // g_sum
    k_zero_f<<<(2048 + T - 1) / T, T>>>(sq, 1024);
    k_zero_i<<<(NN + T - 1) / T, T>>>(hist, NN);

    // stacked weights
    k_copy<<<(3 * 64 * 128 + T - 1) / T, T>>>(wcat1, rg1_wrel, 3 * 64 * 128);
    k_copy<<<(64 * 128 + T - 1) / T, T>>>(wcat1 + 3 * 64 * 128, rg1_wroot, 64 * 128);
    k_copy<<<(3 * 128 * 128 + T - 1) / T, T>>>(wcat2, rg2_wrel, 3 * 128 * 128);
    k_copy<<<(128 * 128 + T - 1) / T, T>>>(wcat2 + 3 * 128 * 128, rg2_wroot, 128 * 128);

    // CSR build
    k_hist<<<(EE + T - 1) / T, T>>>(dst);
    k_scan1<<<NB1, 512>>>();
    k_scan2<<<1, 256>>>();
    k_scan3<<<NB1, 512>>>();
    k_place<<<(EE + T - 1) / T, T>>>(src, dst, et);

    // ---- MLP branch (uses bufA; must finish before GNN reuses it) ----
    sgemm_bias<<<dim3(2, gy, 1), T>>>(x, mlp_w1, mlp_b1, bufA, NN, 64, 256);
    k_colstats<<<512, 256>>>(bufA, sum + 0, sq + 0);
    k_bnrelu<<<(NN * 256 + T - 1) / T, T>>>(bufA, 256, sum + 0, sq + 0, mlp_g1, mlp_be1, NN * 256);
    sgemm_bias<<<dim3(1, gy, 1), T>>>(bufA, mlp_w2, mlp_b2, zmlp, NN, 256, 128);
    k_colstats<<<512, 128>>>(zmlp, sum + 256, sq + 256);
    k_bnrelu<<<(NN * 128 + T - 1) / T, T>>>(zmlp, 128, sum + 256, sq + 256, mlp_g2, mlp_be2, NN * 128);

    // ---- GNN branch ----
    int nodeGrid = (NN * 32 + T - 1) / T;
    k_asda<<<nodeGrid, T>>>(x, hsd);                 // h_in -> bufA slot3
    k_agg1<<<nodeGrid, T>>>();                       // per-rel agg -> bufA slots 0-2
    sgemm_bias<<<dim3(1, gy, 1), T>>>(bufA, wcat1, rg1_b, agg1, NN, 256, 128);
    k_colstats<<<512, 128>>>(agg1, sum + 512, sq + 512);
    k_bnrelu<<<(NN * 128 + T - 1) / T, T>>>(agg1, 128, sum + 512, sq + 512, bn1_g, bn1_b, NN * 128);

    k_agg2<<<nodeGrid, T>>>();                       // per-rel agg + z1 -> A2
    sgemm_bias<<<dim3(1, gy, 1), T>>>(A2, wcat2, rg2_b, agg2, NN, 512, 128);
    k_colstats<<<512, 128>>>(agg2, sum + 768, sq + 768);
    k_bnrelu<<<(NN * 128 + T - 1) / T, T>>>(agg2, 128, sum + 768, sq + 768, bn2_g, bn2_b, NN * 128);

    // ---- head ----
    k_final<<<(NN * 32 + T - 1) / T, T>>>(out_w, out_b, out);
}

// round 4
// speedup vs baseline: 1.7924x; 1.1174x over previous
#include <cuda_runtime.h>

#define NN 100000
#define EE 1600000
#define EPS 1e-5f
#define NB1 196   // ceil(NN/512)

// ---------------- scratch ---------------------------------------------------
__device__ float g_bufA[NN * 256];     // MLP hidden (track A only)
__device__ float g_A1[NN * 256];       // [agg_r0|agg_r1|agg_r2|h_in] (track B)
__device__ float g_zmlp[NN * 128];
__device__ float g_A2[(long)NN * 512]; // [agg_r0|agg_r1|agg_r2|z1]
__device__ float g_agg1[NN * 128];     // z1
__device__ float g_agg2[NN * 128];     // z2
__device__ float g_wcat[256 * 128 + 512 * 128];
__device__ float g_sum[4 * 256];
__device__ float g_sq[4 * 256];
__device__ int   g_hist[NN];
__device__ int   g_row[NN];
__device__ int   g_cur[NN];
__device__ int   g_incl[NN];
__device__ int   g_bsum[256];
__device__ int   g_packed[EE];         // src | (rel<<20)

// ---------------- utility ---------------------------------------------------
__global__ void k_zero_i(int* p, int n) {
    int i = blockIdx.x * blockDim.x + threadIdx.x;
    if (i < n) p[i] = 0;
}
__global__ void k_zero_f(float* p, int n) {
    int i = blockIdx.x * blockDim.x + threadIdx.x;
    if (i < n) p[i] = 0.0f;
}
__global__ void k_copy(float* dst, const float* __restrict__ src, int n) {
    int i = blockIdx.x * blockDim.x + threadIdx.x;
    if (i < n) dst[i] = src[i];
}

// ---------------- CSR build --------------------------------------------------
__global__ void k_hist(const int* __restrict__ dst) {
    int i = blockIdx.x * blockDim.x + threadIdx.x;
    if (i < EE) atomicAdd(&g_hist[dst[i]], 1);
}
__global__ void k_scan1() {
    __shared__ int sm[512];
    int i = blockIdx.x * 512 + threadIdx.x;
    int v = (i < NN) ? g_hist[i] : 0;
    sm[threadIdx.x] = v;
    __syncthreads();
    for (int off = 1; off < 512; off <<= 1) {
        int t = (threadIdx.x >= off) ? sm[threadIdx.x - off] : 0;
        __syncthreads();
        sm[threadIdx.x] += t;
        __syncthreads();
    }
    if (i < NN) g_incl[i] = sm[threadIdx.x];
    if (threadIdx.x == 511) g_bsum[blockIdx.x] = sm[511];
}
__global__ void k_scan2() {
    __shared__ int sm[256];
    int t = threadIdx.x;
    int v = (t < NB1) ? g_bsum[t] : 0;
    sm[t] = v;
    __syncthreads();
    for (int off = 1; off < 256; off <<= 1) {
        int u = (t >= off) ? sm[t - off] : 0;
        __syncthreads();
        sm[t] += u;
        __syncthreads();
    }
    if (t < NB1) g_bsum[t] = sm[t] - v;  // exclusive
}
__global__ void k_scan3() {
    int i = blockIdx.x * 512 + threadIdx.x;
    if (i >= NN) return;
    int r = g_incl[i] - g_hist[i] + g_bsum[blockIdx.x];
    g_row[i] = r;
    g_cur[i] = r;
}
__global__ void k_place(const int* __restrict__ src, const int* __restrict__ dst,
                        const int* __restrict__ et) {
    int i = blockIdx.x * blockDim.x + threadIdx.x;
    if (i >= EE) return;
    int pos = atomicAdd(&g_cur[dst[i]], 1);
    g_packed[pos] = src[i] | (et[i] << 20);
}

// ---------------- SGEMM ------------------------------------------------------
#define BM 128
#define BN 128
#define BKK 16
#define TM 8
#define TN 8

__global__ __launch_bounds__(256)
void sgemm_bias(const float* __restrict__ A, const float* __restrict__ B,
                const float* __restrict__ bias, float* __restrict__ C,
                int M, int K, int Nc) {
    __shared__ float As[BKK][BM];
    __shared__ float Bs[BKK][BN];

    int tid = threadIdx.x;
    int tcol = tid % (BN / TN);
    int trow = tid / (BN / TN);
    int rowBase = blockIdx.y * BM;
    int colBase = blockIdx.x * BN;

    float acc[TM][TN];
#pragma unroll
    for (int i = 0; i < TM; i++)
#pragma unroll
        for (int j = 0; j < TN; j++) acc[i][j] = 0.0f;

    int aRow = tid / 4, aCol4 = tid % 4;
    int bRow = tid / 32, bCol4 = tid % 32;

    for (int k0 = 0; k0 < K; k0 += BKK) {
#pragma unroll
        for (int i = 0; i < 2; i++) {
            int r = aRow + i * 64;
            int grow = rowBase + r;
            float4 v = make_float4(0.f, 0.f, 0.f, 0.f);
            if (grow < M) v = *(const float4*)&A[(long)grow * K + k0 + aCol4 * 4];
            As[aCol4 * 4 + 0][r] = v.x;
            As[aCol4 * 4 + 1][r] = v.y;
            As[aCol4 * 4 + 2][r] = v.z;
            As[aCol4 * 4 + 3][r] = v.w;
        }
#pragma unroll
        for (int i = 0; i < 2; i++) {
            int r = bRow + i * 8;
            float4 v = *(const float4*)&B[(long)(k0 + r) * Nc + colBase + bCol4 * 4];
            *(float4*)&Bs[r][bCol4 * 4] = v;
        }
        __syncthreads();

#pragma unroll
        for (int kk = 0; kk < BKK; kk++) {
            float ra[TM], rb[TN];
            *(float4*)&ra[0] = *(const float4*)&As[kk][trow * TM];
            *(float4*)&ra[4] = *(const float4*)&As[kk][trow * TM + 4];
            *(float4*)&rb[0] = *(const float4*)&Bs[kk][tcol * TN];
            *(float4*)&rb[4] = *(const float4*)&Bs[kk][tcol * TN + 4];
#pragma unroll
            for (int i = 0; i < TM; i++)
#pragma unroll
                for (int j = 0; j < TN; j++) acc[i][j] = fmaf(ra[i], rb[j], acc[i][j]);
        }
        __syncthreads();
    }

#pragma unroll
    for (int i = 0; i < TM; i++) {
        int grow = rowBase + trow * TM + i;
        if (grow >= M) continue;
#pragma unroll
        for (int j = 0; j < TN; j++) {
            int col = colBase + tcol * TN + j;
            C[(long)grow * Nc + col] = acc[i][j] + bias[col];
        }
    }
}

// ---------------- BN ---------------------------------------------------------
__global__ void k_colstats(const float* __restrict__ z, float* sum, float* sq) {
    int C = blockDim.x;
    int t = threadIdx.x;
    float s = 0.f, q = 0.f;
    for (int r = blockIdx.x; r < NN; r += gridDim.x) {
        float v = z[(long)r * C + t];
        s += v;
        q += v * v;
    }
    atomicAdd(&sum[t], s);
    atomicAdd(&sq[t], q);
}
__global__ void k_bnrelu(float* z, int C, const float* __restrict__ sum,
                         const float* __restrict__ sq, const float* __restrict__ gam,
                         const float* __restrict__ bet, int total) {
    int i = blockIdx.x * blockDim.x + threadIdx.x;
    if (i >= total) return;
    int c = i % C;
    const float invN = 1.0f / (float)NN;
    float m = sum[c] * invN;
    float var = sq[c] * invN - m * m;
    float v = (z[i] - m) * rsqrtf(var + EPS) * gam[c] + bet[c];
    z[i] = fmaxf(v, 0.0f);
}

// ---------------- ASDA (CSR, warp per node) ---------------------------------
__global__ __launch_bounds__(256)
void k_asda(const float* __restrict__ x, const float* __restrict__ hsd) {
    int node = (blockIdx.x * blockDim.x + threadIdx.x) >> 5;
    int lane = threadIdx.x & 31;
    if (node >= NN) return;
    int start = g_row[node];
    int end = start + g_hist[node];
    float hd = hsd[node];

    float den = 0.f;
    for (int base = start; base < end; base += 32) {
        int idx = base + lane;
        float e = 0.f;
        if (idx < end) {
            int s = g_packed[idx] & 0xFFFFF;
            e = __expf((hsd[s] - hd) * 10.0f);
        }
        den += e;
    }
#pragma unroll
    for (int o = 16; o > 0; o >>= 1) den += __shfl_xor_sync(0xffffffffu, den, o);
    float inv = 1.0f / fmaxf(den, 1e-9f);

    float a0 = x[(long)node * 64 + lane];
    float a1 = x[(long)node * 64 + 32 + lane];
    for (int base = start; base < end; base += 32) {
        int idx = base + lane;
        int v = 0;
        float al = 0.f;
        if (idx < end) {
            v = g_packed[idx];
            int s = v & 0xFFFFF;
            al = __expf((hsd[s] - hd) * 10.0f) * inv;
        }
        int m = min(32, end - base);
        for (int j = 0; j < m; j++) {
            int vv = __shfl_sync(0xffffffffu, v, j);
            float aa = __shfl_sync(0xffffffffu, al, j);
            int s = vv & 0xFFFFF;
            a0 = fmaf(aa, x[(long)s * 64 + lane], a0);
            a1 = fmaf(aa, x[(long)s * 64 + 32 + lane], a1);
        }
    }
    g_A1[(long)node * 256 + 192 + lane] = a0;   // h_in -> A1 slot 3
    g_A1[(long)node * 256 + 224 + lane] = a1;
}

// ---------------- RGCN layer-1 input aggregation (dim 64) --------------------
__global__ __launch_bounds__(256)
void k_agg1() {
    int node = (blockIdx.x * blockDim.x + threadIdx.x) >> 5;
    int lane = threadIdx.x & 31;
    if (node >= NN) return;
    int start = g_row[node];
    int end = start + g_hist[node];

    float a00 = 0, a01 = 0, a10 = 0, a11 = 0, a20 = 0, a21 = 0;
    int c0 = 0, c1 = 0, c2 = 0;
    for (int base = start; base < end; base += 32) {
        int idx = base + lane;
        int v = (idx < end) ? g_packed[idx] : 0;
        int m = min(32, end - base);
        for (int j = 0; j < m; j++) {
            int vv = __shfl_sync(0xffffffffu, v, j);
            int s = vv & 0xFFFFF;
            int r = vv >> 20;
            float f0 = g_A1[(long)s * 256 + 192 + lane];
            float f1 = g_A1[(long)s * 256 + 224 + lane];
            if (r == 0)      { a00 += f0; a01 += f1; c0++; }
            else if (r == 1) { a10 += f0; a11 += f1; c1++; }
            else             { a20 += f0; a21 += f1; c2++; }
        }
    }
    float w0 = 1.0f / (float)max(c0, 1);
    float w1 = 1.0f / (float)max(c1, 1);
    float w2 = 1.0f / (float)max(c2, 1);
    long b = (long)node * 256;
    g_A1[b + 0 + lane] = a00 * w0;  g_A1[b + 32 + lane] = a01 * w0;
    g_A1[b + 64 + lane] = a10 * w1; g_A1[b + 96 + lane] = a11 * w1;
    g_A1[b + 128 + lane] = a20 * w2; g_A1[b + 160 + lane] = a21 * w2;
}

// ---------------- RGCN layer-2 input aggregation (dim 128) -------------------
__global__ __launch_bounds__(256)
void k_agg2() {
    int node = (blockIdx.x * blockDim.x + threadIdx.x) >> 5;
    int lane = threadIdx.x & 31;
    if (node >= NN) return;
    int start = g_row[node];
    int end = start + g_hist[node];

    float acc[3][4] = {};
    int cnt[3] = {0, 0, 0};
    for (int base = start; base < end; base += 32) {
        int idx = base + lane;
        int v = (idx < end) ? g_packed[idx] : 0;
        int m = min(32, end - base);
        for (int j = 0; j < m; j++) {
            int vv = __shfl_sync(0xffffffffu, v, j);
            int s = vv & 0xFFFFF;
            int r = vv >> 20;
            long sb = (long)s * 128;
            float f0 = g_agg1[sb + lane];
            float f1 = g_agg1[sb + 32 + lane];
            float f2 = g_agg1[sb + 64 + lane];
            float f3 = g_agg1[sb + 96 + lane];
            if (r == 0)      { acc[0][0] += f0; acc[0][1] += f1; acc[0][2] += f2; acc[0][3] += f3; cnt[0]++; }
            else if (r == 1) { acc[1][0] += f0; acc[1][1] += f1; acc[1][2] += f2; acc[1][3] += f3; cnt[1]++; }
            else             { acc[2][0] += f0; acc[2][1] += f1; acc[2][2] += f2; acc[2][3] += f3; cnt[2]++; }
        }
    }
    long b = (long)node * 512;
#pragma unroll
    for (int r = 0; r < 3; r++) {
        float w = 1.0f / (float)max(cnt[r], 1);
#pragma unroll
        for (int k = 0; k < 4; k++)
            g_A2[b + r * 128 + k * 32 + lane] = acc[r][k] * w;
    }
    long zb = (long)node * 128;
#pragma unroll
    for (int k = 0; k < 4; k++)
        g_A2[b + 384 + k * 32 + lane] = g_agg1[zb + k * 32 + lane];
}

// ---------------- head -------------------------------------------------------
__global__ void k_final(const float* __restrict__ ow, const float* __restrict__ ob,
                        float* __restrict__ out) {
    int g = blockIdx.x * blockDim.x + threadIdx.x;
    int node = g >> 5;
    int lane = g & 31;
    if (node >= NN) return;
    float4 a = *(const float4*)&g_zmlp[(long)node * 128 + lane * 4];
    float4 w1 = *(const float4*)&ow[lane * 4];
    float4 b = *(const float4*)&g_agg2[(long)node * 128 + lane * 4];
    float4 w2 = *(const float4*)&ow[128 + lane * 4];
    float sum = a.x * w1.x + a.y * w1.y + a.z * w1.z + a.w * w1.w +
                b.x * w2.x + b.y * w2.y + b.z * w2.z + b.w * w2.w;
#pragma unroll
    for (int off = 16; off > 0; off >>= 1) sum += __shfl_down_sync(0xffffffffu, sum, off);
    if (lane == 0) out[node] = sum + ob[0];
}

// ---------------- host -------------------------------------------------------
extern "C" void kernel_launch(void* const* d_in, const int* in_sizes, int n_in,
                              void* d_out, int out_size) {
    const float* x       = (const float*)d_in[0];
    const float* hsd     = (const float*)d_in[1];
    const int*   ei      = (const int*)d_in[2];
    const int*   et      = (const int*)d_in[3];
    const float* mlp_w1  = (const float*)d_in[4];
    const float* mlp_b1  = (const float*)d_in[5];
    const float* mlp_g1  = (const float*)d_in[6];
    const float* mlp_be1 = (const float*)d_in[7];
    const float* mlp_w2  = (const float*)d_in[8];
    const float* mlp_b2  = (const float*)d_in[9];
    const float* mlp_g2  = (const float*)d_in[10];
    const float* mlp_be2 = (const float*)d_in[11];
    const float* rg1_wrel  = (const float*)d_in[12];
    const float* rg1_wroot = (const float*)d_in[13];
    const float* rg1_b     = (const float*)d_in[14];
    const float* bn1_g     = (const float*)d_in[15];
    const float* bn1_b     = (const float*)d_in[16];
    const float* rg2_wrel  = (const float*)d_in[17];
    const float* rg2_wroot = (const float*)d_in[18];
    const float* rg2_b     = (const float*)d_in[19];
    const float* bn2_g     = (const float*)d_in[20];
    const float* bn2_b     = (const float*)d_in[21];
    const float* out_w     = (const float*)d_in[22];
    const float* out_b     = (const float*)d_in[23];
    const int* src = ei;
    const int* dst = ei + EE;
    float* out = (float*)d_out;

    float *bufA, *A1, *zmlp, *A2, *agg1, *agg2, *wcat, *sum, *sq;
    int *hist;
    cudaGetSymbolAddress((void**)&bufA, g_bufA);
    cudaGetSymbolAddress((void**)&A1, g_A1);
    cudaGetSymbolAddress((void**)&zmlp, g_zmlp);
    cudaGetSymbolAddress((void**)&A2, g_A2);
    cudaGetSymbolAddress((void**)&agg1, g_agg1);
    cudaGetSymbolAddress((void**)&agg2, g_agg2);
    cudaGetSymbolAddress((void**)&wcat, g_wcat);
    cudaGetSymbolAddress((void**)&sum, g_sum);
    cudaGetSymbolAddress((void**)&sq, g_sq);
    cudaGetSymbolAddress((void**)&hist, g_hist);

    const int T = 256;
    int gy = (NN + BM - 1) / BM;  // 782
    float* wcat1 = wcat;
    float* wcat2 = wcat + 256 * 128;
    int nodeGrid = (NN * 32 + T - 1) / T;

    // side stream + fork/join events (created fresh each call; capture-legal)
    cudaStream_t s0 = 0, sB;
    cudaStreamCreate(&sB);
    cudaEvent_t evFork, evJoin;
    cudaEventCreateWithFlags(&evFork, cudaEventDisableTiming);
    cudaEventCreateWithFlags(&evJoin, cudaEventDisableTiming);

    // --- prologue on s0 (launches 0-1) ---
    k_zero_f<<<(1024 + T - 1) / T, T, 0, s0>>>(sum, 1024);
    k_zero_f<<<(1024 + T - 1) / T, T, 0, s0>>>(sq, 1024);

    // fork: sB branches off after stats-zeroing
    cudaEventRecord(evFork, s0);
    cudaStreamWaitEvent(sB, evFork, 0);

    // --- track B prefix (launches 2-4) ---
    k_zero_i<<<(NN + T - 1) / T, T, 0, sB>>>(hist, NN);
    k_copy<<<(3 * 64 * 128 + T - 1) / T, T, 0, sB>>>(wcat1, rg1_wrel, 3 * 64 * 128);
    k_copy<<<(64 * 128 + T - 1) / T, T, 0, sB>>>(wcat1 + 3 * 64 * 128, rg1_wroot, 64 * 128);

    // --- track A: MLP branch (first sgemm = launch index 5 -> ncu captures it) ---
    sgemm_bias<<<dim3(2, gy, 1), T, 0, s0>>>(x, mlp_w1, mlp_b1, bufA, NN, 64, 256);
    k_colstats<<<512, 256, 0, s0>>>(bufA, sum + 0, sq + 0);
    k_bnrelu<<<(NN * 256 + T - 1) / T, T, 0, s0>>>(bufA, 256, sum + 0, sq + 0, mlp_g1, mlp_be1, NN * 256);
    sgemm_bias<<<dim3(1, gy, 1), T, 0, s0>>>(bufA, mlp_w2, mlp_b2, zmlp, NN, 256, 128);
    k_colstats<<<512, 128, 0, s0>>>(zmlp, sum + 256, sq + 256);
    k_bnrelu<<<(NN * 128 + T - 1) / T, T, 0, s0>>>(zmlp, 128, sum + 256, sq + 256, mlp_g2, mlp_be2, NN * 128);

    // --- track B: CSR build + GNN branch ---
    k_copy<<<(3 * 128 * 128 + T - 1) / T, T, 0, sB>>>(wcat2, rg2_wrel, 3 * 128 * 128);
    k_copy<<<(128 * 128 + T - 1) / T, T, 0, sB>>>(wcat2 + 3 * 128 * 128, rg2_wroot, 128 * 128);
    k_hist<<<(EE + T - 1) / T, T, 0, sB>>>(dst);
    k_scan1<<<NB1, 512, 0, sB>>>();
    k_scan2<<<1, 256, 0, sB>>>();
    k_scan3<<<NB1, 512, 0, sB>>>();
    k_place<<<(EE + T - 1) / T, T, 0, sB>>>(src, dst, et);

    k_asda<<<nodeGrid, T, 0, sB>>>(x, hsd);
    k_agg1<<<nodeGrid, T, 0, sB>>>();
    sgemm_bias<<<dim3(1, gy, 1), T, 0, sB>>>(A1, wcat1, rg1_b, agg1, NN, 256, 128);
    k_colstats<<<512, 128, 0, sB>>>(agg1, sum + 512, sq + 512);
    k_bnrelu<<<(NN * 128 + T - 1) / T, T, 0, sB>>>(agg1, 128, sum + 512, sq + 512, bn1_g, bn1_b, NN * 128);

    k_agg2<<<nodeGrid, T, 0, sB>>>();
    sgemm_bias<<<dim3(1, gy, 1), T, 0, sB>>>(A2, wcat2, rg2_b, agg2, NN, 512, 128);
    k_colstats<<<512, 128, 0, sB>>>(agg2, sum + 768, sq + 768);
    k_bnrelu<<<(NN * 128 + T - 1) / T, T, 0, sB>>>(agg2, 128, sum + 768, sq + 768, bn2_g, bn2_b, NN * 128);

    // join
    cudaEventRecord(evJoin, sB);
    cudaStreamWaitEvent(s0, evJoin, 0);

    // ---- head ----
    k_final<<<(NN * 32 + T - 1) / T, T, 0, s0>>>(out_w, out_b, out);
}

// round 6
// speedup vs baseline: 1.8124x; 1.0112x over previous
#include <cuda_runtime.h>

#define NN 100000
#define EE 1600000
#define EPS 1e-5f
#define NB1 196        // ceil(NN/512)
#define MSPLIT 50048   // 391 * 128

// ---------------- scratch ---------------------------------------------------
__device__ float g_bufA[NN * 256];     // MLP hidden (track A only)
__device__ float g_A1[NN * 256];       // [agg_r0|agg_r1|agg_r2|h_in] (track B)
__device__ float g_zmlp[NN * 128];
__device__ float g_A2[(long)NN * 512]; // [agg_r0|agg_r1|agg_r2|z1]
__device__ float g_agg1[NN * 128];     // z1
__device__ float g_agg2[NN * 128];     // z2
__device__ float g_wcat[256 * 128 + 512 * 128];
__device__ float g_sum[4 * 256];       // per-stage column sums -> scale
__device__ float g_sq[4 * 256];        // per-stage column sumsq -> shift
__device__ int   g_hist[NN];
__device__ int   g_row[NN];
__device__ int   g_cur[NN];
__device__ int   g_incl[NN];
__device__ int   g_bsum[256];
__device__ int   g_packed[EE];         // src | (rel<<20)

// ---------------- utility ---------------------------------------------------
__global__ void k_zero_i(int* p, int n) {
    int i = blockIdx.x * blockDim.x + threadIdx.x;
    if (i < n) p[i] = 0;
}
__global__ void k_zero_f(float* p, int n) {
    int i = blockIdx.x * blockDim.x + threadIdx.x;
    if (i < n) p[i] = 0.0f;
}
__global__ void k_copy(float* dst, const float* __restrict__ src, int n) {
    int i = blockIdx.x * blockDim.x + threadIdx.x;
    if (i < n) dst[i] = src[i];
}

// ---------------- CSR build --------------------------------------------------
__global__ void k_hist(const int* __restrict__ dst) {
    int i = blockIdx.x * blockDim.x + threadIdx.x;
    if (i < EE) atomicAdd(&g_hist[dst[i]], 1);
}
__global__ void k_scan1() {
    __shared__ int sm[512];
    int i = blockIdx.x * 512 + threadIdx.x;
    int v = (i < NN) ? g_hist[i] : 0;
    sm[threadIdx.x] = v;
    __syncthreads();
    for (int off = 1; off < 512; off <<= 1) {
        int t = (threadIdx.x >= off) ? sm[threadIdx.x - off] : 0;
        __syncthreads();
        sm[threadIdx.x] += t;
        __syncthreads();
    }
    if (i < NN) g_incl[i] = sm[threadIdx.x];
    if (threadIdx.x == 511) g_bsum[blockIdx.x] = sm[511];
}
__global__ void k_scan2() {
    __shared__ int sm[256];
    int t = threadIdx.x;
    int v = (t < NB1) ? g_bsum[t] : 0;
    sm[t] = v;
    __syncthreads();
    for (int off = 1; off < 256; off <<= 1) {
        int u = (t >= off) ? sm[t - off] : 0;
        __syncthreads();
        sm[t] += u;
        __syncthreads();
    }
    if (t < NB1) g_bsum[t] = sm[t] - v;  // exclusive
}
__global__ void k_scan3() {
    int i = blockIdx.x * 512 + threadIdx.x;
    if (i >= NN) return;
    int r = g_incl[i] - g_hist[i] + g_bsum[blockIdx.x];
    g_row[i] = r;
    g_cur[i] = r;
}
__global__ void k_place(const int* __restrict__ src, const int* __restrict__ dst,
                        const int* __restrict__ et) {
    int i = blockIdx.x * blockDim.x + threadIdx.x;
    if (i >= EE) return;
    int pos = atomicAdd(&g_cur[dst[i]], 1);
    g_packed[pos] = src[i] | (et[i] << 20);
}

// ---------------- SGEMM with fused column-stats ------------------------------
#define BM 128
#define BN 128
#define BKK 16
#define TM 8
#define TN 8

__global__ __launch_bounds__(256)
void sgemm_bias(const float* __restrict__ A, const float* __restrict__ B,
                const float* __restrict__ bias, float* __restrict__ C,
                int M, int K, int Nc, int lda,
                float* sumP, float* sqP) {
    __shared__ float As[BKK][BM];
    __shared__ float Bs[BKK][BN];
    __shared__ float csum[BN];
    __shared__ float csq[BN];

    int tid = threadIdx.x;
    int tcol = tid % (BN / TN);
    int trow = tid / (BN / TN);
    int rowBase = blockIdx.y * BM;
    int colBase = blockIdx.x * BN;

    if (sumP && tid < BN) { csum[tid] = 0.0f; csq[tid] = 0.0f; }

    float acc[TM][TN];
#pragma unroll
    for (int i = 0; i < TM; i++)
#pragma unroll
        for (int j = 0; j < TN; j++) acc[i][j] = 0.0f;

    int aRow = tid / 4, aCol4 = tid % 4;
    int bRow = tid / 32, bCol4 = tid % 32;

    for (int k0 = 0; k0 < K; k0 += BKK) {
#pragma unroll
        for (int i = 0; i < 2; i++) {
            int r = aRow + i * 64;
            int grow = rowBase + r;
            float4 v = make_float4(0.f, 0.f, 0.f, 0.f);
            if (grow < M) v = *(const float4*)&A[(long)grow * lda + k0 + aCol4 * 4];
            As[aCol4 * 4 + 0][r] = v.x;
            As[aCol4 * 4 + 1][r] = v.y;
            As[aCol4 * 4 + 2][r] = v.z;
            As[aCol4 * 4 + 3][r] = v.w;
        }
#pragma unroll
        for (int i = 0; i < 2; i++) {
            int r = bRow + i * 8;
            float4 v = *(const float4*)&B[(long)(k0 + r) * Nc + colBase + bCol4 * 4];
            *(float4*)&Bs[r][bCol4 * 4] = v;
        }
        __syncthreads();

#pragma unroll
        for (int kk = 0; kk < BKK; kk++) {
            float ra[TM], rb[TN];
            *(float4*)&ra[0] = *(const float4*)&As[kk][trow * TM];
            *(float4*)&ra[4] = *(const float4*)&As[kk][trow * TM + 4];
            *(float4*)&rb[0] = *(const float4*)&Bs[kk][tcol * TN];
            *(float4*)&rb[4] = *(const float4*)&Bs[kk][tcol * TN + 4];
#pragma unroll
            for (int i = 0; i < TM; i++)
#pragma unroll
                for (int j = 0; j < TN; j++) acc[i][j] = fmaf(ra[i], rb[j], acc[i][j]);
        }
        __syncthreads();
    }

    // epilogue: bias, write, and per-column partial stats
#pragma unroll
    for (int j = 0; j < TN; j++) {
        int col = colBase + tcol * TN + j;
        float bv = bias[col];
        float s = 0.f, q = 0.f;
#pragma unroll
        for (int i = 0; i < TM; i++) {
            int grow = rowBase + trow * TM + i;
            if (grow < M) {
                float v = acc[i][j] + bv;
                C[(long)grow * Nc + col] = v;
                s += v;
                q += v * v;
            }
        }
        if (sumP) {
            atomicAdd(&csum[tcol * TN + j], s);
            atomicAdd(&csq[tcol * TN + j], q);
        }
    }
    if (sumP) {
        __syncthreads();
        if (tid < BN) {
            atomicAdd(&sumP[colBase + tid], csum[tid]);
            atomicAdd(&sqP[colBase + tid], csq[tid]);
        }
    }
}

// ---------------- BN ---------------------------------------------------------
__global__ void k_bnprep(float* sum, float* sq, const float* __restrict__ g,
                         const float* __restrict__ b, int C) {
    int c = threadIdx.x;
    if (c >= C) return;
    const float invN = 1.0f / (float)NN;
    float m = sum[c] * invN;
    float var = sq[c] * invN - m * m;
    float sc = g[c] * rsqrtf(var + EPS);
    float sh = b[c] - m * sc;
    sum[c] = sc;
    sq[c] = sh;
}
__global__ void k_bnrelu(float* z, int C, const float* __restrict__ sc,
                         const float* __restrict__ sh, int total) {
    int i = blockIdx.x * blockDim.x + threadIdx.x;
    if (i >= total) return;
    int c = i % C;
    z[i] = fmaxf(fmaf(z[i], sc[c], sh[c]), 0.0f);
}

// ---------------- ASDA (CSR, warp per node) ---------------------------------
__global__ __launch_bounds__(256)
void k_asda(const float* __restrict__ x, const float* __restrict__ hsd) {
    int node = (blockIdx.x * blockDim.x + threadIdx.x) >> 5;
    int lane = threadIdx.x & 31;
    if (node >= NN) return;
    int start = g_row[node];
    int end = start + g_hist[node];
    float hd = hsd[node];

    float den = 0.f;
    for (int base = start; base < end; base += 32) {
        int idx = base + lane;
        float e = 0.f;
        if (idx < end) {
            int s = g_packed[idx] & 0xFFFFF;
            e = __expf((hsd[s] - hd) * 10.0f);
        }
        den += e;
    }
#pragma unroll
    for (int o = 16; o > 0; o >>= 1) den += __shfl_xor_sync(0xffffffffu, den, o);
    float inv = 1.0f / fmaxf(den, 1e-9f);

    float a0 = x[(long)node * 64 + lane];
    float a1 = x[(long)node * 64 + 32 + lane];
    for (int base = start; base < end; base += 32) {
        int idx = base + lane;
        int v = 0;
        float al = 0.f;
        if (idx < end) {
            v = g_packed[idx];
            int s = v & 0xFFFFF;
            al = __expf((hsd[s] - hd) * 10.0f) * inv;
        }
        int m = min(32, end - base);
        for (int j = 0; j < m; j++) {
            int vv = __shfl_sync(0xffffffffu, v, j);
            float aa = __shfl_sync(0xffffffffu, al, j);
            int s = vv & 0xFFFFF;
            a0 = fmaf(aa, x[(long)s * 64 + lane], a0);
            a1 = fmaf(aa, x[(long)s * 64 + 32 + lane], a1);
        }
    }
    g_A1[(long)node * 256 + 192 + lane] = a0;   // h_in -> A1 slot 3
    g_A1[(long)node * 256 + 224 + lane] = a1;
}

// ---------------- RGCN layer-1 input aggregation (dim 64) --------------------
__global__ __launch_bounds__(256)
void k_agg1() {
    int node = (blockIdx.x * blockDim.x + threadIdx.x) >> 5;
    int lane = threadIdx.x & 31;
    if (node >= NN) return;
    int start = g_row[node];
    int end = start + g_hist[node];

    float a00 = 0, a01 = 0, a10 = 0, a11 = 0, a20 = 0, a21 = 0;
    int c0 = 0, c1 = 0, c2 = 0;
    for (int base = start; base < end; base += 32) {
        int idx = base + lane;
        int v = (idx < end) ? g_packed[idx] : 0;
        int m = min(32, end - base);
        for (int j = 0; j < m; j++) {
            int vv = __shfl_sync(0xffffffffu, v, j);
            int s = vv & 0xFFFFF;
            int r = vv >> 20;
            float f0 = g_A1[(long)s * 256 + 192 + lane];
            float f1 = g_A1[(long)s * 256 + 224 + lane];
            if (r == 0)      { a00 += f0; a01 += f1; c0++; }
            else if (r == 1) { a10 += f0; a11 += f1; c1++; }
            else             { a20 += f0; a21 += f1; c2++; }
        }
    }
    float w0 = 1.0f / (float)max(c0, 1);
    float w1 = 1.0f / (float)max(c1, 1);
    float w2 = 1.0f / (float)max(c2, 1);
    long b = (long)node * 256;
    g_A1[b + 0 + lane] = a00 * w0;  g_A1[b + 32 + lane] = a01 * w0;
    g_A1[b + 64 + lane] = a10 * w1; g_A1[b + 96 + lane] = a11 * w1;
    g_A1[b + 128 + lane] = a20 * w2; g_A1[b + 160 + lane] = a21 * w2;
}

// ---------------- RGCN layer-2 input aggregation (dim 128) -------------------
__global__ __launch_bounds__(256)
void k_agg2() {
    int node = (blockIdx.x * blockDim.x + threadIdx.x) >> 5;
    int lane = threadIdx.x & 31;
    if (node >= NN) return;
    int start = g_row[node];
    int end = start + g_hist[node];

    float acc[3][4] = {};
    int cnt[3] = {0, 0, 0};
    for (int base = start; base < end; base += 32) {
        int idx = base + lane;
        int v = (idx < end) ? g_packed[idx] : 0;
        int m = min(32, end - base);
        for (int j = 0; j < m; j++) {
            int vv = __shfl_sync(0xffffffffu, v, j);
            int s = vv & 0xFFFFF;
            int r = vv >> 20;
            long sb = (long)s * 128;
            float f0 = g_agg1[sb + lane];
            float f1 = g_agg1[sb + 32 + lane];
            float f2 = g_agg1[sb + 64 + lane];
            float f3 = g_agg1[sb + 96 + lane];
            if (r == 0)      { acc[0][0] += f0; acc[0][1] += f1; acc[0][2] += f2; acc[0][3] += f3; cnt[0]++; }
            else if (r == 1) { acc[1][0] += f0; acc[1][1] += f1; acc[1][2] += f2; acc[1][3] += f3; cnt[1]++; }
            else             { acc[2][0] += f0; acc[2][1] += f1; acc[2][2] += f2; acc[2][3] += f3; cnt[2]++; }
        }
    }
    long b = (long)node * 512;
#pragma unroll
    for (int r = 0; r < 3; r++) {
        float w = 1.0f / (float)max(cnt[r], 1);
#pragma unroll
        for (int k = 0; k < 4; k++)
            g_A2[b + r * 128 + k * 32 + lane] = acc[r][k] * w;
    }
    long zb = (long)node * 128;
#pragma unroll
    for (int k = 0; k < 4; k++)
        g_A2[b + 384 + k * 32 + lane] = g_agg1[zb + k * 32 + lane];
}

// ---------------- head -------------------------------------------------------
__global__ void k_final(const float* __restrict__ ow, const float* __restrict__ ob,
                        float* __restrict__ out) {
    int g = blockIdx.x * blockDim.x + threadIdx.x;
    int node = g >> 5;
    int lane = g & 31;
    if (node >= NN) return;
    float4 a = *(const float4*)&g_zmlp[(long)node * 128 + lane * 4];
    float4 w1 = *(const float4*)&ow[lane * 4];
    float4 b = *(const float4*)&g_agg2[(long)node * 128 + lane * 4];
    float4 w2 = *(const float4*)&ow[128 + lane * 4];
    float sum = a.x * w1.x + a.y * w1.y + a.z * w1.z + a.w * w1.w +
                b.x * w2.x + b.y * w2.y + b.z * w2.z + b.w * w2.w;
#pragma unroll
    for (int off = 16; off > 0; off >>= 1) sum += __shfl_down_sync(0xffffffffu, sum, off);
    if (lane == 0) out[node] = sum + ob[0];
}

// ---------------- host -------------------------------------------------------
extern "C" void kernel_launch(void* const* d_in, const int* in_sizes, int n_in,
                              void* d_out, int out_size) {
    const float* x       = (const float*)d_in[0];
    const float* hsd     = (const float*)d_in[1];
    const int*   ei      = (const int*)d_in[2];
    const int*   et      = (const int*)d_in[3];
    const float* mlp_w1  = (const float*)d_in[4];
    const float* mlp_b1  = (const float*)d_in[5];
    const float* mlp_g1  = (const float*)d_in[6];
    const float* mlp_be1 = (const float*)d_in[7];
    const float* mlp_w2  = (const float*)d_in[8];
    const float* mlp_b2  = (const float*)d_in[9];
    const float* mlp_g2  = (const float*)d_in[10];
    const float* mlp_be2 = (const float*)d_in[11];
    const float* rg1_wrel  = (const float*)d_in[12];
    const float* rg1_wroot = (const float*)d_in[13];
    const float* rg1_b     = (const float*)d_in[14];
    const float* bn1_g     = (const float*)d_in[15];
    const float* bn1_b     = (const float*)d_in[16];
    const float* rg2_wrel  = (const float*)d_in[17];
    const float* rg2_wroot = (const float*)d_in[18];
    const float* rg2_b     = (const float*)d_in[19];
    const float* bn2_g     = (const float*)d_in[20];
    const float* bn2_b     = (const float*)d_in[21];
    const float* out_w     = (const float*)d_in[22];
    const float* out_b     = (const float*)d_in[23];
    const int* src = ei;
    const int* dst = ei + EE;
    float* out = (float*)d_out;

    float *bufA, *A1, *zmlp, *A2, *agg1, *agg2, *wcat, *sum, *sq;
    int *hist;
    cudaGetSymbolAddress((void**)&bufA, g_bufA);
    cudaGetSymbolAddress((void**)&A1, g_A1);
    cudaGetSymbolAddress((void**)&zmlp, g_zmlp);
    cudaGetSymbolAddress((void**)&A2, g_A2);
    cudaGetSymbolAddress((void**)&agg1, g_agg1);
    cudaGetSymbolAddress((void**)&agg2, g_agg2);
    cudaGetSymbolAddress((void**)&wcat, g_wcat);
    cudaGetSymbolAddress((void**)&sum, g_sum);
    cudaGetSymbolAddress((void**)&sq, g_sq);
    cudaGetSymbolAddress((void**)&hist, g_hist);

    const int T = 256;
    float* wcat1 = wcat;
    float* wcat2 = wcat + 256 * 128;
    int nodeGrid = (NN * 32 + T - 1) / T;

    // M split: lo half on B, hi half on A
    const int M_LO = MSPLIT;                 // 50048 rows -> 391 blocks
    const int M_HI = NN - MSPLIT;            // 49952 rows -> 391 blocks
    int gyLo = M_LO / BM;                    // 391
    int gyHi = (M_HI + BM - 1) / BM;         // 391
    int gyAll = (NN + BM - 1) / BM;          // 782

    cudaStream_t s0 = 0, sB;
    cudaStreamCreate(&sB);
    cudaEvent_t evFork, evAgg1, evG1A, evAgg2, evG2A, evJoin;
    cudaEventCreateWithFlags(&evFork, cudaEventDisableTiming);
    cudaEventCreateWithFlags(&evAgg1, cudaEventDisableTiming);
    cudaEventCreateWithFlags(&evG1A, cudaEventDisableTiming);
    cudaEventCreateWithFlags(&evAgg2, cudaEventDisableTiming);
    cudaEventCreateWithFlags(&evG2A, cudaEventDisableTiming);
    cudaEventCreateWithFlags(&evJoin, cudaEventDisableTiming);

    // --- prologue on s0 ---
    k_zero_f<<<4, T, 0, s0>>>(sum, 1024);
    k_zero_f<<<4, T, 0, s0>>>(sq, 1024);
    cudaEventRecord(evFork, s0);
    cudaStreamWaitEvent(sB, evFork, 0);

    // --- track B: CSR + weight stacking ---
    k_zero_i<<<(NN + T - 1) / T, T, 0, sB>>>(hist, NN);
    k_copy<<<(3 * 64 * 128 + T - 1) / T, T, 0, sB>>>(wcat1, rg1_wrel, 3 * 64 * 128);
    k_copy<<<(64 * 128 + T - 1) / T, T, 0, sB>>>(wcat1 + 3 * 64 * 128, rg1_wroot, 64 * 128);
    k_copy<<<(3 * 128 * 128 + T - 1) / T, T, 0, sB>>>(wcat2, rg2_wrel, 3 * 128 * 128);
    k_copy<<<(128 * 128 + T - 1) / T, T, 0, sB>>>(wcat2 + 3 * 128 * 128, rg2_wroot, 128 * 128);
    k_hist<<<(EE + T - 1) / T, T, 0, sB>>>(dst);
    k_scan1<<<NB1, 512, 0, sB>>>();
    k_scan2<<<1, 256, 0, sB>>>();
    k_scan3<<<NB1, 512, 0, sB>>>();
    k_place<<<(EE + T - 1) / T, T, 0, sB>>>(src, dst, et);
    k_asda<<<nodeGrid, T, 0, sB>>>(x, hsd);
    k_agg1<<<nodeGrid, T, 0, sB>>>();
    cudaEventRecord(evAgg1, sB);

    // --- track A: MLP branch ---
    sgemm_bias<<<dim3(2, gyAll, 1), T, 0, s0>>>(x, mlp_w1, mlp_b1, bufA, NN, 64, 256, 64, sum + 0, sq + 0);
    k_bnprep<<<1, 256, 0, s0>>>(sum + 0, sq + 0, mlp_g1, mlp_be1, 256);
    k_bnrelu<<<(NN * 256 + T - 1) / T, T, 0, s0>>>(bufA, 256, sum + 0, sq + 0, NN * 256);
    sgemm_bias<<<dim3(1, gyAll, 1), T, 0, s0>>>(bufA, mlp_w2, mlp_b2, zmlp, NN, 256, 128, 256, sum + 256, sq + 256);
    k_bnprep<<<1, 128, 0, s0>>>(sum + 256, sq + 256, mlp_g2, mlp_be2, 128);
    k_bnrelu<<<(NN * 128 + T - 1) / T, T, 0, s0>>>(zmlp, 128, sum + 256, sq + 256, NN * 128);

    // --- GNN GEMM 1, M-split across streams ---
    cudaStreamWaitEvent(s0, evAgg1, 0);
    sgemm_bias<<<dim3(1, gyHi, 1), T, 0, s0>>>(A1 + (long)MSPLIT * 256, wcat1, rg1_b,
                                               agg1 + (long)MSPLIT * 128, M_HI, 256, 128, 256,
                                               sum + 512, sq + 512);
    cudaEventRecord(evG1A, s0);
    sgemm_bias<<<dim3(1, gyLo, 1), T, 0, sB>>>(A1, wcat1, rg1_b, agg1, M_LO, 256, 128, 256,
                                               sum + 512, sq + 512);
    cudaStreamWaitEvent(sB, evG1A, 0);
    k_bnprep<<<1, 128, 0, sB>>>(sum + 512, sq + 512, bn1_g, bn1_b, 128);
    k_bnrelu<<<(NN * 128 + T - 1) / T, T, 0, sB>>>(agg1, 128, sum + 512, sq + 512, NN * 128);

    // --- layer 2 aggregation + M-split GEMM ---
    k_agg2<<<nodeGrid, T, 0, sB>>>();
    cudaEventRecord(evAgg2, sB);
    cudaStreamWaitEvent(s0, evAgg2, 0);
    sgemm_bias<<<dim3(1, gyHi, 1), T, 0, s0>>>(A2 + (long)MSPLIT * 512, wcat2, rg2_b,
                                               agg2 + (long)MSPLIT * 128, M_HI, 512, 128, 512,
                                               sum + 768, sq + 768);
    cudaEventRecord(evG2A, s0);
    sgemm_bias<<<dim3(1, gyLo, 1), T, 0, sB>>>(A2, wcat2, rg2_b, agg2, M_LO, 512, 128, 512,
                                               sum + 768, sq + 768);
    cudaStreamWaitEvent(sB, evG2A, 0);
    k_bnprep<<<1, 128, 0, sB>>>(sum + 768, sq + 768, bn2_g, bn2_b, 128);
    k_bnrelu<<<(NN * 128 + T - 1) / T, T, 0, sB>>>(agg2, 128, sum + 768, sq + 768, NN * 128);

    // join + head
    cudaEventRecord(evJoin, sB);
    cudaStreamWaitEvent(s0, evJoin, 0);
    k_final<<<(NN * 32 + T - 1) / T, T, 0, s0>>>(out_w, out_b, out);
}

// round 7
// speedup vs baseline: 2.1676x; 1.1960x over previous
#include <cuda_runtime.h>

#define NN 100000
#define EE 1600000
#define EPS 1e-5f
#define NB1 196        // ceil(NN/512)
#define MSPLIT 50048   // 391 * 128

// ---------------- scratch ---------------------------------------------------
__device__ float g_bufA[NN * 256];     // MLP hidden raw (track A only)
__device__ float g_A1[NN * 256];       // [agg_r0|agg_r1|agg_r2|h_in] (track B)
__device__ float g_zmlp[NN * 128];     // raw mlp2 output (BN fused into k_final)
__device__ float g_A2[(long)NN * 512]; // [agg_r0|agg_r1|agg_r2|z1]
__device__ float g_agg1[NN * 128];     // raw rgcn1 output (BN fused into k_agg2)
__device__ float g_agg2[NN * 128];     // raw rgcn2 output (BN fused into k_final)
__device__ float g_wcat[256 * 128 + 512 * 128];
__device__ float g_sum[4 * 256];       // col sums -> bn scale after k_bnprep
__device__ float g_sq[4 * 256];        // col sumsq -> bn shift after k_bnprep
__device__ int   g_hist[NN];
__device__ int   g_row[NN];
__device__ int   g_cur[NN];
__device__ int   g_incl[NN];
__device__ int   g_bsum[256];
__device__ int   g_packed[EE];         // src | (rel<<20)

// ---------------- f32x2 helpers ---------------------------------------------
typedef unsigned long long ull;
__device__ __forceinline__ ull pack2(float v) {
    ull r;
    asm("mov.b64 %0, {%1, %1};" : "=l"(r) : "f"(v));
    return r;
}
__device__ __forceinline__ void fma2(ull& d, ull a, ull b) {
    asm("fma.rn.f32x2 %0, %1, %2, %0;" : "+l"(d) : "l"(a), "l"(b));
}
__device__ __forceinline__ float2 unpack2(ull v) {
    float2 f;
    asm("mov.b64 {%0, %1}, %2;" : "=f"(f.x), "=f"(f.y) : "l"(v));
    return f;
}

// ---------------- utility ---------------------------------------------------
__global__ void k_zero_i(int* p, int n) {
    int i = blockIdx.x * blockDim.x + threadIdx.x;
    if (i < n) p[i] = 0;
}
__global__ void k_zero_f2(float* p, float* q, int n) {
    int i = blockIdx.x * blockDim.x + threadIdx.x;
    if (i < n) { p[i] = 0.0f; q[i] = 0.0f; }
}
// stack [rg1_wrel | rg1_wroot] and [rg2_wrel | rg2_wroot]
__global__ void k_copy_w(float* w1, const float* __restrict__ r1rel, const float* __restrict__ r1root,
                         float* w2, const float* __restrict__ r2rel, const float* __restrict__ r2root) {
    int i = blockIdx.x * blockDim.x + threadIdx.x;
    if (i < 3 * 64 * 128) w1[i] = r1rel[i];
    else if (i < 4 * 64 * 128) w1[i] = r1root[i - 3 * 64 * 128];
    if (i < 3 * 128 * 128) w2[i] = r2rel[i];
    else if (i < 4 * 128 * 128) w2[i] = r2root[i - 3 * 128 * 128];
}

// ---------------- CSR build --------------------------------------------------
__global__ void k_hist(const int* __restrict__ dst) {
    int i = blockIdx.x * blockDim.x + threadIdx.x;
    if (i < EE) atomicAdd(&g_hist[dst[i]], 1);
}
__global__ void k_scan1() {
    __shared__ int sm[512];
    int i = blockIdx.x * 512 + threadIdx.x;
    int v = (i < NN) ? g_hist[i] : 0;
    sm[threadIdx.x] = v;
    __syncthreads();
    for (int off = 1; off < 512; off <<= 1) {
        int t = (threadIdx.x >= off) ? sm[threadIdx.x - off] : 0;
        __syncthreads();
        sm[threadIdx.x] += t;
        __syncthreads();
    }
    if (i < NN) g_incl[i] = sm[threadIdx.x];
    if (threadIdx.x == 511) g_bsum[blockIdx.x] = sm[511];
}
__global__ void k_scan2() {
    __shared__ int sm[256];
    int t = threadIdx.x;
    int v = (t < NB1) ? g_bsum[t] : 0;
    sm[t] = v;
    __syncthreads();
    for (int off = 1; off < 256; off <<= 1) {
        int u = (t >= off) ? sm[t - off] : 0;
        __syncthreads();
        sm[t] += u;
        __syncthreads();
    }
    if (t < NB1) g_bsum[t] = sm[t] - v;  // exclusive
}
__global__ void k_scan3() {
    int i = blockIdx.x * 512 + threadIdx.x;
    if (i >= NN) return;
    int r = g_incl[i] - g_hist[i] + g_bsum[blockIdx.x];
    g_row[i] = r;
    g_cur[i] = r;
}
__global__ void k_place(const int* __restrict__ src, const int* __restrict__ dst,
                        const int* __restrict__ et) {
    int i = blockIdx.x * blockDim.x + threadIdx.x;
    if (i >= EE) return;
    int pos = atomicAdd(&g_cur[dst[i]], 1);
    g_packed[pos] = src[i] | (et[i] << 20);
}

// ---------------- SGEMM (f32x2) with fused col-stats + fused A-side BN -------
#define BM 128
#define BN 128
#define BKK 16
#define TM 8
#define TN 8
#define TN2 4

__global__ __launch_bounds__(256)
void sgemm_bias(const float* __restrict__ A, const float* __restrict__ B,
                const float* __restrict__ bias, float* __restrict__ C,
                int M, int K, int Nc, int lda,
                float* sumP, float* sqP,
                const float* __restrict__ aSc, const float* __restrict__ aSh) {
    __shared__ float As[BKK][BM];
    __shared__ float Bs[BKK][BN];
    __shared__ float csum[BN];
    __shared__ float csq[BN];

    int tid = threadIdx.x;
    int tcol = tid % (BN / TN);
    int trow = tid / (BN / TN);
    int rowBase = blockIdx.y * BM;
    int colBase = blockIdx.x * BN;

    if (sumP && tid < BN) { csum[tid] = 0.0f; csq[tid] = 0.0f; }

    ull acc2[TM][TN2];
#pragma unroll
    for (int i = 0; i < TM; i++)
#pragma unroll
        for (int j = 0; j < TN2; j++) acc2[i][j] = 0ull;

    int aRow = tid / 4, aCol4 = tid % 4;
    int bRow = tid / 32, bCol4 = tid % 32;

    for (int k0 = 0; k0 < K; k0 += BKK) {
#pragma unroll
        for (int i = 0; i < 2; i++) {
            int r = aRow + i * 64;
            int grow = rowBase + r;
            float4 v = make_float4(0.f, 0.f, 0.f, 0.f);
            if (grow < M) {
                v = *(const float4*)&A[(long)grow * lda + k0 + aCol4 * 4];
                if (aSc) {
                    int kb = k0 + aCol4 * 4;
                    v.x = fmaxf(fmaf(v.x, aSc[kb + 0], aSh[kb + 0]), 0.0f);
                    v.y = fmaxf(fmaf(v.y, aSc[kb + 1], aSh[kb + 1]), 0.0f);
                    v.z = fmaxf(fmaf(v.z, aSc[kb + 2], aSh[kb + 2]), 0.0f);
                    v.w = fmaxf(fmaf(v.w, aSc[kb + 3], aSh[kb + 3]), 0.0f);
                }
            }
            As[aCol4 * 4 + 0][r] = v.x;
            As[aCol4 * 4 + 1][r] = v.y;
            As[aCol4 * 4 + 2][r] = v.z;
            As[aCol4 * 4 + 3][r] = v.w;
        }
#pragma unroll
        for (int i = 0; i < 2; i++) {
            int r = bRow + i * 8;
            float4 v = *(const float4*)&B[(long)(k0 + r) * Nc + colBase + bCol4 * 4];
            *(float4*)&Bs[r][bCol4 * 4] = v;
        }
        __syncthreads();

#pragma unroll
        for (int kk = 0; kk < BKK; kk++) {
            float ra[TM];
            ull rb2[TN2];
            *(float4*)&ra[0] = *(const float4*)&As[kk][trow * TM];
            *(float4*)&ra[4] = *(const float4*)&As[kk][trow * TM + 4];
            const ull* bp = (const ull*)&Bs[kk][tcol * TN];
            rb2[0] = bp[0]; rb2[1] = bp[1]; rb2[2] = bp[2]; rb2[3] = bp[3];
#pragma unroll
            for (int i = 0; i < TM; i++) {
                ull a2 = pack2(ra[i]);
#pragma unroll
                for (int j = 0; j < TN2; j++) fma2(acc2[i][j], a2, rb2[j]);
            }
        }
        __syncthreads();
    }

    // epilogue: bias, write, per-column partial stats
#pragma unroll
    for (int jp = 0; jp < TN2; jp++) {
        int col = colBase + tcol * TN + jp * 2;
        float bv0 = bias[col], bv1 = bias[col + 1];
        float s0 = 0.f, q0 = 0.f, s1 = 0.f, q1 = 0.f;
#pragma unroll
        for (int i = 0; i < TM; i++) {
            int grow = rowBase + trow * TM + i;
            if (grow < M) {
                float2 p = unpack2(acc2[i][jp]);
                p.x += bv0; p.y += bv1;
                *(float2*)&C[(long)grow * Nc + col] = p;
                s0 += p.x; q0 += p.x * p.x;
                s1 += p.y; q1 += p.y * p.y;
            }
        }
        if (sumP) {
            atomicAdd(&csum[tcol * TN + jp * 2], s0);
            atomicAdd(&csq[tcol * TN + jp * 2], q0);
            atomicAdd(&csum[tcol * TN + jp * 2 + 1], s1);
            atomicAdd(&csq[tcol * TN + jp * 2 + 1], q1);
        }
    }
    if (sumP) {
        __syncthreads();
        if (tid < BN) {
            atomicAdd(&sumP[colBase + tid], csum[tid]);
            atomicAdd(&sqP[colBase + tid], csq[tid]);
        }
    }
}

// ---------------- BN prep (stats -> scale/shift in place) --------------------
__global__ void k_bnprep(float* sum, float* sq, const float* __restrict__ g,
                         const float* __restrict__ b, int C) {
    int c = threadIdx.x;
    if (c >= C) return;
    const float invN = 1.0f / (float)NN;
    float m = sum[c] * invN;
    float var = sq[c] * invN - m * m;
    float sc = g[c] * rsqrtf(var + EPS);
    float sh = b[c] - m * sc;
    sum[c] = sc;
    sq[c] = sh;
}

// ---------------- ASDA (CSR, warp per node) ---------------------------------
__global__ __launch_bounds__(256)
void k_asda(const float* __restrict__ x, const float* __restrict__ hsd) {
    int node = (blockIdx.x * blockDim.x + threadIdx.x) >> 5;
    int lane = threadIdx.x & 31;
    if (node >= NN) return;
    int start = g_row[node];
    int end = start + g_hist[node];
    float hd = hsd[node];

    float den = 0.f;
    for (int base = start; base < end; base += 32) {
        int idx = base + lane;
        float e = 0.f;
        if (idx < end) {
            int s = g_packed[idx] & 0xFFFFF;
            e = __expf((hsd[s] - hd) * 10.0f);
        }
        den += e;
    }
#pragma unroll
    for (int o = 16; o > 0; o >>= 1) den += __shfl_xor_sync(0xffffffffu, den, o);
    float inv = 1.0f / fmaxf(den, 1e-9f);

    float a0 = x[(long)node * 64 + lane];
    float a1 = x[(long)node * 64 + 32 + lane];
    for (int base = start; base < end; base += 32) {
        int idx = base + lane;
        int v = 0;
        float al = 0.f;
        if (idx < end) {
            v = g_packed[idx];
            int s = v & 0xFFFFF;
            al = __expf((hsd[s] - hd) * 10.0f) * inv;
        }
        int m = min(32, end - base);
        for (int j = 0; j < m; j++) {
            int vv = __shfl_sync(0xffffffffu, v, j);
            float aa = __shfl_sync(0xffffffffu, al, j);
            int s = vv & 0xFFFFF;
            a0 = fmaf(aa, x[(long)s * 64 + lane], a0);
            a1 = fmaf(aa, x[(long)s * 64 + 32 + lane], a1);
        }
    }
    g_A1[(long)node * 256 + 192 + lane] = a0;
    g_A1[(long)node * 256 + 224 + lane] = a1;
}

// ---------------- RGCN layer-1 input aggregation (dim 64) --------------------
__global__ __launch_bounds__(256)
void k_agg1() {
    int node = (blockIdx.x * blockDim.x + threadIdx.x) >> 5;
    int lane = threadIdx.x & 31;
    if (node >= NN) return;
    int start = g_row[node];
    int end = start + g_hist[node];

    float a00 = 0, a01 = 0, a10 = 0, a11 = 0, a20 = 0, a21 = 0;
    int c0 = 0, c1 = 0, c2 = 0;
    for (int base = start; base < end; base += 32) {
        int idx = base + lane;
        int v = (idx < end) ? g_packed[idx] : 0;
        int m = min(32, end - base);
        for (int j = 0; j < m; j++) {
            int vv = __shfl_sync(0xffffffffu, v, j);
            int s = vv & 0xFFFFF;
            int r = vv >> 20;
            float f0 = g_A1[(long)s * 256 + 192 + lane];
            float f1 = g_A1[(long)s * 256 + 224 + lane];
            if (r == 0)      { a00 += f0; a01 += f1; c0++; }
            else if (r == 1) { a10 += f0; a11 += f1; c1++; }
            else             { a20 += f0; a21 += f1; c2++; }
        }
    }
    float w0 = 1.0f / (float)max(c0, 1);
    float w1 = 1.0f / (float)max(c1, 1);
    float w2 = 1.0f / (float)max(c2, 1);
    long b = (long)node * 256;
    g_A1[b + 0 + lane] = a00 * w0;  g_A1[b + 32 + lane] = a01 * w0;
    g_A1[b + 64 + lane] = a10 * w1; g_A1[b + 96 + lane] = a11 * w1;
    g_A1[b + 128 + lane] = a20 * w2; g_A1[b + 160 + lane] = a21 * w2;
}

// ------- RGCN layer-2 aggregation (dim 128) with fused BN1+relu on gather ----
__global__ __launch_bounds__(256)
void k_agg2(const float* __restrict__ sc, const float* __restrict__ sh) {
    int node = (blockIdx.x * blockDim.x + threadIdx.x) >> 5;
    int lane = threadIdx.x & 31;
    if (node >= NN) return;
    int start = g_row[node];
    int end = start + g_hist[node];

    float sc0 = sc[lane], sc1 = sc[lane + 32], sc2 = sc[lane + 64], sc3 = sc[lane + 96];
    float sh0 = sh[lane], sh1 = sh[lane + 32], sh2 = sh[lane + 64], sh3 = sh[lane + 96];

    float acc[3][4] = {};
    int cnt[3] = {0, 0, 0};
    for (int base = start; base < end; base += 32) {
        int idx = base + lane;
        int v = (idx < end) ? g_packed[idx] : 0;
        int m = min(32, end - base);
        for (int j = 0; j < m; j++) {
            int vv = __shfl_sync(0xffffffffu, v, j);
            int s = vv & 0xFFFFF;
            int r = vv >> 20;
            long sb = (long)s * 128;
            float f0 = fmaxf(fmaf(g_agg1[sb + lane],      sc0, sh0), 0.0f);
            float f1 = fmaxf(fmaf(g_agg1[sb + 32 + lane], sc1, sh1), 0.0f);
            float f2 = fmaxf(fmaf(g_agg1[sb + 64 + lane], sc2, sh2), 0.0f);
            float f3 = fmaxf(fmaf(g_agg1[sb + 96 + lane], sc3, sh3), 0.0f);
            if (r == 0)      { acc[0][0] += f0; acc[0][1] += f1; acc[0][2] += f2; acc[0][3] += f3; cnt[0]++; }
            else if (r == 1) { acc[1][0] += f0; acc[1][1] += f1; acc[1][2] += f2; acc[1][3] += f3; cnt[1]++; }
            else             { acc[2][0] += f0; acc[2][1] += f1; acc[2][2] += f2; acc[2][3] += f3; cnt[2]++; }
        }
    }
    long b = (long)node * 512;
#pragma unroll
    for (int r = 0; r < 3; r++) {
        float w = 1.0f / (float)max(cnt[r], 1);
#pragma unroll
        for (int k = 0; k < 4; k++)
            g_A2[b + r * 128 + k * 32 + lane] = acc[r][k] * w;
    }
    long zb = (long)node * 128;
    g_A2[b + 384 + lane]      = fmaxf(fmaf(g_agg1[zb + lane],      sc0, sh0), 0.0f);
    g_A2[b + 384 + 32 + lane] = fmaxf(fmaf(g_agg1[zb + 32 + lane], sc1, sh1), 0.0f);
    g_A2[b + 384 + 64 + lane] = fmaxf(fmaf(g_agg1[zb + 64 + lane], sc2, sh2), 0.0f);
    g_A2[b + 384 + 96 + lane] = fmaxf(fmaf(g_agg1[zb + 96 + lane], sc3, sh3), 0.0f);
}

// ---------------- head with fused BN(mlp2) + BN(bn2) + relu ------------------
__global__ void k_final(const float* __restrict__ ow, const float* __restrict__ ob,
                        const float* __restrict__ scm, const float* __restrict__ shm,
                        const float* __restrict__ scg, const float* __restrict__ shg,
                        float* __restrict__ out) {
    int g = blockIdx.x * blockDim.x + threadIdx.x;
    int node = g >> 5;
    int lane = g & 31;
    if (node >= NN) return;
    float4 a  = *(const float4*)&g_zmlp[(long)node * 128 + lane * 4];
    float4 sm = *(const float4*)&scm[lane * 4];
    float4 hm = *(const float4*)&shm[lane * 4];
    float4 w1 = *(const float4*)&ow[lane * 4];
    float4 b  = *(const float4*)&g_agg2[(long)node * 128 + lane * 4];
    float4 sg = *(const float4*)&scg[lane * 4];
    float4 hg = *(const float4*)&shg[lane * 4];
    float4 w2 = *(const float4*)&ow[128 + lane * 4];
    float sum =
        fmaxf(fmaf(a.x, sm.x, hm.x), 0.f) * w1.x + fmaxf(fmaf(a.y, sm.y, hm.y), 0.f) * w1.y +
        fmaxf(fmaf(a.z, sm.z, hm.z), 0.f) * w1.z + fmaxf(fmaf(a.w, sm.w, hm.w), 0.f) * w1.w +
        fmaxf(fmaf(b.x, sg.x, hg.x), 0.f) * w2.x + fmaxf(fmaf(b.y, sg.y, hg.y), 0.f) * w2.y +
        fmaxf(fmaf(b.z, sg.z, hg.z), 0.f) * w2.z + fmaxf(fmaf(b.w, sg.w, hg.w), 0.f) * w2.w;
#pragma unroll
    for (int off = 16; off > 0; off >>= 1) sum += __shfl_down_sync(0xffffffffu, sum, off);
    if (lane == 0) out[node] = sum + ob[0];
}

// ---------------- host -------------------------------------------------------
extern "C" void kernel_launch(void* const* d_in, const int* in_sizes, int n_in,
                              void* d_out, int out_size) {
    const float* x       = (const float*)d_in[0];
    const float* hsd     = (const float*)d_in[1];
    const int*   ei      = (const int*)d_in[2];
    const int*   et      = (const int*)d_in[3];
    const float* mlp_w1  = (const float*)d_in[4];
    const float* mlp_b1  = (const float*)d_in[5];
    const float* mlp_g1  = (const float*)d_in[6];
    const float* mlp_be1 = (const float*)d_in[7];
    const float* mlp_w2  = (const float*)d_in[8];
    const float* mlp_b2  = (const float*)d_in[9];
    const float* mlp_g2  = (const float*)d_in[10];
    const float* mlp_be2 = (const float*)d_in[11];
    const float* rg1_wrel  = (const float*)d_in[12];
    const float* rg1_wroot = (const float*)d_in[13];
    const float* rg1_b     = (const float*)d_in[14];
    const float* bn1_g     = (const float*)d_in[15];
    const float* bn1_b     = (const float*)d_in[16];
    const float* rg2_wrel  = (const float*)d_in[17];
    const float* rg2_wroot = (const float*)d_in[18];
    const float* rg2_b     = (const float*)d_in[19];
    const float* bn2_g     = (const float*)d_in[20];
    const float* bn2_b     = (const float*)d_in[21];
    const float* out_w     = (const float*)d_in[22];
    const float* out_b     = (const float*)d_in[23];
    const int* src = ei;
    const int* dst = ei + EE;
    float* out = (float*)d_out;

    float *bufA, *A1, *zmlp, *A2, *agg1, *agg2, *wcat, *sum, *sq;
    int *hist;
    cudaGetSymbolAddress((void**)&bufA, g_bufA);
    cudaGetSymbolAddress((void**)&A1, g_A1);
    cudaGetSymbolAddress((void**)&zmlp, g_zmlp);
    cudaGetSymbolAddress((void**)&A2, g_A2);
    cudaGetSymbolAddress((void**)&agg1, g_agg1);
    cudaGetSymbolAddress((void**)&agg2, g_agg2);
    cudaGetSymbolAddress((void**)&wcat, g_wcat);
    cudaGetSymbolAddress((void**)&sum, g_sum);
    cudaGetSymbolAddress((void**)&sq, g_sq);
    cudaGetSymbolAddress((void**)&hist, g_hist);

    const int T = 256;
    float* wcat1 = wcat;
    float* wcat2 = wcat + 256 * 128;
    int nodeGrid = (NN * 32 + T - 1) / T;

    const int M_LO = MSPLIT;
    const int M_HI = NN - MSPLIT;
    int gyLo = M_LO / BM;                    // 391
    int gyHi = (M_HI + BM - 1) / BM;         // 391
    int gyAll = (NN + BM - 1) / BM;          // 782

    cudaStream_t s0 = 0, sB;
    cudaStreamCreate(&sB);
    cudaEvent_t evFork, evAgg1, evG1A, evAgg2, evG2A, evJoin;
    cudaEventCreateWithFlags(&evFork, cudaEventDisableTiming);
    cudaEventCreateWithFlags(&evAgg1, cudaEventDisableTiming);
    cudaEventCreateWithFlags(&evG1A, cudaEventDisableTiming);
    cudaEventCreateWithFlags(&evAgg2, cudaEventDisableTiming);
    cudaEventCreateWithFlags(&evG2A, cudaEventDisableTiming);
    cudaEventCreateWithFlags(&evJoin, cudaEventDisableTiming);

    // --- prologue on s0 ---
    k_zero_f2<<<4, T, 0, s0>>>(sum, sq, 1024);
    cudaEventRecord(evFork, s0);
    cudaStreamWaitEvent(sB, evFork, 0);

    // --- track B: CSR + weight stacking ---
    k_zero_i<<<(NN + T - 1) / T, T, 0, sB>>>(hist, NN);
    k_copy_w<<<(4 * 128 * 128 + T - 1) / T, T, 0, sB>>>(wcat1, rg1_wrel, rg1_wroot,
                                                        wcat2, rg2_wrel, rg2_wroot);
    k_hist<<<(EE + T - 1) / T, T, 0, sB>>>(dst);
    k_scan1<<<NB1, 512, 0, sB>>>();
    k_scan2<<<1, 256, 0, sB>>>();
    k_scan3<<<NB1, 512, 0, sB>>>();
    k_place<<<(EE + T - 1) / T, T, 0, sB>>>(src, dst, et);
    k_asda<<<nodeGrid, T, 0, sB>>>(x, hsd);
    k_agg1<<<nodeGrid, T, 0, sB>>>();
    cudaEventRecord(evAgg1, sB);

    // --- track A: MLP branch (BN1 fused into mlp2 A-load; BN2 fused into k_final) ---
    sgemm_bias<<<dim3(2, gyAll, 1), T, 0, s0>>>(x, mlp_w1, mlp_b1, bufA, NN, 64, 256, 64,
                                                sum + 0, sq + 0, nullptr, nullptr);
    k_bnprep<<<1, 256, 0, s0>>>(sum + 0, sq + 0, mlp_g1, mlp_be1, 256);
    sgemm_bias<<<dim3(1, gyAll, 1), T, 0, s0>>>(bufA, mlp_w2, mlp_b2, zmlp, NN, 256, 128, 256,
                                                sum + 256, sq + 256, sum + 0, sq + 0);
    k_bnprep<<<1, 128, 0, s0>>>(sum + 256, sq + 256, mlp_g2, mlp_be2, 128);

    // --- GNN GEMM 1, M-split across streams ---
    cudaStreamWaitEvent(s0, evAgg1, 0);
    sgemm_bias<<<dim3(1, gyHi, 1), T, 0, s0>>>(A1 + (long)MSPLIT * 256, wcat1, rg1_b,
                                               agg1 + (long)MSPLIT * 128, M_HI, 256, 128, 256,
                                               sum + 512, sq + 512, nullptr, nullptr);
    cudaEventRecord(evG1A, s0);
    sgemm_bias<<<dim3(1, gyLo, 1), T, 0, sB>>>(A1, wcat1, rg1_b, agg1, M_LO, 256, 128, 256,
                                               sum + 512, sq + 512, nullptr, nullptr);
    cudaStreamWaitEvent(sB, evG1A, 0);
    k_bnprep<<<1, 128, 0, sB>>>(sum + 512, sq + 512, bn1_g, bn1_b, 128);

    // --- layer 2 aggregation (fused BN1+relu) + M-split GEMM ---
    k_agg2<<<nodeGrid, T, 0, sB>>>(sum + 512, sq + 512);
    cudaEventRecord(evAgg2, sB);
    cudaStreamWaitEvent(s0, evAgg2, 0);
    sgemm_bias<<<dim3(1, gyHi, 1), T, 0, s0>>>(A2 + (long)MSPLIT * 512, wcat2, rg2_b,
                                               agg2 + (long)MSPLIT * 128, M_HI, 512, 128, 512,
                                               sum + 768, sq + 768, nullptr, nullptr);
    cudaEventRecord(evG2A, s0);
    sgemm_bias<<<dim3(1, gyLo, 1), T, 0, sB>>>(A2, wcat2, rg2_b, agg2, M_LO, 512, 128, 512,
                                               sum + 768, sq + 768, nullptr, nullptr);
    cudaStreamWaitEvent(sB, evG2A, 0);
    k_bnprep<<<1, 128, 0, sB>>>(sum + 768, sq + 768, bn2_g, bn2_b, 128);

    // join + head (fused BN(mlp2)+BN2+relu)
    cudaEventRecord(evJoin, sB);
    cudaStreamWaitEvent(s0, evJoin, 0);
    k_final<<<(NN * 32 + T - 1) / T, T, 0, s0>>>(out_w, out_b,
                                                 sum + 256, sq + 256,
                                                 sum + 768, sq + 768, out);
}